// round 5
// baseline (speedup 1.0000x reference)
#include <cuda_runtime.h>
#include <cstdint>

// ---------------------------------------------------------------------------
// GCN: 4 conv layers + global max pool + MLP.
// R5: warp-aligned divergence-free gathers (packed int2 CSR, shfl combine),
// float4 smem reads in GEMM (stride 68), merged preprocessing, Ax fused into
// norm_fill via red.add.
// ---------------------------------------------------------------------------

constexpr int NN = 100000;
constexpr int EE = 1600000;
constexpr int GG = 64;

__device__ __align__(16) float g_deg[NN];            // deg, then dis (in place)
__device__ __align__(16) int   g_src[EE];
__device__ __align__(16) int   g_dst[EE];
__device__ __align__(16) int2  g_cpack[EE];          // CSR: (src, norm-bits) by dst
__device__ __align__(16) int   g_off[NN + 1];
__device__ __align__(16) int   g_cnt[NN];
__device__ __align__(16) int   g_cur[NN];
__device__ __align__(16) int   g_aux[128];
__device__ __align__(16) float g_ax[NN];
__device__ __align__(16) float g_A[(size_t)NN * 128];
__device__ __align__(16) float g_B[(size_t)NN * 128];
__device__ __align__(16) float g_C[(size_t)NN * 128];
__device__ __align__(16) float g_pool[GG * 32];
__device__ int g_is64;

__device__ __forceinline__ void red_add_f32(float* p, float v) {
    asm volatile("red.global.add.f32 [%0], %1;" :: "l"(p), "f"(v) : "memory");
}

// ---------------- init + dtype detect ----------------
// int64 node ids < 2^31 => every odd 32-bit word is 0. int32 => random ids.
__global__ void k_init_detect(const int* __restrict__ raw, int n) {
    int i = blockIdx.x * blockDim.x + threadIdx.x;
    if (i < n) {
        g_deg[i] = 1.0f;   // self loop weight
        g_cnt[i] = 0;
        g_cur[i] = 0;
    }
    if (blockIdx.x == 0) {
        __shared__ int any;
        if (threadIdx.x == 0) any = 0;
        __syncthreads();
        int v = 0;
        for (int k = threadIdx.x; k < 2048; k += blockDim.x) v |= raw[2 * k + 1];
        if (v) atomicOr(&any, 1);
        __syncthreads();
        if (threadIdx.x == 0) g_is64 = (any == 0) ? 1 : 0;
    }
}

__global__ void k_edges_pre(const void* __restrict__ ei,
                            const float* __restrict__ w, int e) {
    int i = blockIdx.x * blockDim.x + threadIdx.x;
    if (i >= e) return;
    int s, d;
    if (g_is64) {
        const long long* p = (const long long*)ei;
        s = (int)p[i];
        d = (int)p[(size_t)e + i];
    } else {
        const int* p = (const int*)ei;
        s = p[i];
        d = p[e + i];
    }
    g_src[i] = s;
    g_dst[i] = d;
    atomicAdd(&g_deg[d], w[i]);
    atomicAdd(&g_cnt[d], 1);
}

// ---------------- scan of g_cnt -> g_off ----------------

__global__ void k_scan1(int n) {   // 1024 threads/block, chunk=1024
    __shared__ int s[1024];
    int t = threadIdx.x;
    int base = blockIdx.x * 1024;
    int v = (base + t < n) ? g_cnt[base + t] : 0;
    s[t] = v;
    __syncthreads();
    for (int d = 1; d < 1024; d <<= 1) {
        int x = (t >= d) ? s[t - d] : 0;
        __syncthreads();
        s[t] += x;
        __syncthreads();
    }
    if (base + t < n) g_off[base + t + 1] = s[t];   // inclusive within chunk
    if (t == 1023) g_aux[blockIdx.x] = s[1023];
}

__global__ void k_scan2(int naux) {  // single block
    __shared__ int s[1024];
    int t = threadIdx.x;
    s[t] = (t < naux) ? g_aux[t] : 0;
    __syncthreads();
    for (int d = 1; d < 1024; d <<= 1) {
        int x = (t >= d) ? s[t - d] : 0;
        __syncthreads();
        s[t] += x;
        __syncthreads();
    }
    if (t < naux) g_aux[t] = (t > 0) ? s[t - 1] : 0;   // exclusive chunk bases
}

// scan fixup + dis + ax self-term init + pool zero, one elementwise pass
__global__ void k_scan3_dis(const float* __restrict__ x, int n) {
    int i = blockIdx.x * blockDim.x + threadIdx.x;
    if (i < GG * 32) g_pool[i] = 0.f;
    if (i >= n) return;
    g_off[i + 1] += g_aux[i >> 10];
    if (i == 0) g_off[0] = 0;
    float dg = g_deg[i];
    float dis = (dg > 0.f) ? rsqrtf(dg) : 0.f;
    g_deg[i] = dis;
    g_ax[i] = dis * dis * x[i];
}

// norm + CSR fill + fused layer-1 Ax accumulation
__global__ void k_norm_fill(const float* __restrict__ w,
                            const float* __restrict__ x, int e) {
    int i = blockIdx.x * blockDim.x + threadIdx.x;
    if (i >= e) return;
    int s = g_src[i];
    int d = g_dst[i];
    float nm = g_deg[s] * w[i] * g_deg[d];
    int pos = g_off[d] + atomicAdd(&g_cur[d], 1);
    g_cpack[pos] = make_int2(s, __float_as_int(nm));
    red_add_f32(&g_ax[d], nm * x[s]);
}

// ---------------- layer 2 GEMM (fused layer-1 expand): FI=128, FO=96 --------
// h1[node][k] = relu(ax[node]*W1[k] + b1[k]) computed on the fly.

__global__ __launch_bounds__(128)
void k_gemm2(const float* __restrict__ W1, const float* __restrict__ b1,
             const float* __restrict__ W2,
             float* __restrict__ tbuf, int n) {
    __shared__ __align__(16) float W1s[128];
    __shared__ __align__(16) float b1s[128];
    __shared__ __align__(16) float Ws[128 * 32];
    const int tid = threadIdx.x;
    const int fo0 = blockIdx.y * 32;
    const int n0 = blockIdx.x * 64;

    W1s[tid] = W1[tid];
    b1s[tid] = b1[tid];
    for (int i = tid; i < 128 * 32; i += 128) {
        int k = i >> 5, j = i & 31;
        Ws[i] = W2[k * 96 + fo0 + j];
    }
    const int fo_t = tid & 7;     // 8 groups of 4 fo
    const int nd_t = tid >> 3;    // 16 groups of 4 nodes
    float axv[4];
#pragma unroll
    for (int i = 0; i < 4; i++) {
        int nd = n0 + nd_t * 4 + i;
        axv[i] = (nd < n) ? g_ax[nd] : 0.f;
    }
    __syncthreads();

    float acc[4][4] = {};
#pragma unroll 8
    for (int k = 0; k < 128; k++) {
        float w1 = W1s[k], bb = b1s[k];
        float4 w = *reinterpret_cast<const float4*>(Ws + k * 32 + fo_t * 4);
#pragma unroll
        for (int i = 0; i < 4; i++) {
            float h = fmaxf(fmaf(axv[i], w1, bb), 0.f);
            acc[i][0] = fmaf(h, w.x, acc[i][0]);
            acc[i][1] = fmaf(h, w.y, acc[i][1]);
            acc[i][2] = fmaf(h, w.z, acc[i][2]);
            acc[i][3] = fmaf(h, w.w, acc[i][3]);
        }
    }
#pragma unroll
    for (int i = 0; i < 4; i++) {
        int nd = n0 + nd_t * 4 + i;
        if (nd >= n) continue;
        size_t off = (size_t)nd * 96 + fo0 + fo_t * 4;
        *reinterpret_cast<float4*>(tbuf + off) =
            make_float4(acc[i][0], acc[i][1], acc[i][2], acc[i][3]);
    }
}

// ---------------- generic GEMM layers 3,4: relu(in+bias) @ W ----------------

template <int FI, int FO>
__global__ __launch_bounds__(128)
void k_gemm(const float* __restrict__ hin, const float* __restrict__ bin,
            const float* __restrict__ W,
            float* __restrict__ tbuf, int n) {
    constexpr int FI4 = FI / 4;
    constexpr int STR = 68;                         // 16B-aligned padded stride
    __shared__ __align__(16) float hsT[FI * STR];   // [k][node]
    __shared__ __align__(16) float Ws[FI * 32];
    __shared__ __align__(16) float bs[FI];
    const int tid = threadIdx.x;
    const int fo0 = blockIdx.y * 32;
    const int n0 = blockIdx.x * 64;

    for (int i = tid; i < FI; i += 128) bs[i] = bin[i];
    for (int i = tid; i < FI * 32; i += 128) {
        int k = i >> 5, j = i & 31;
        Ws[i] = W[k * FO + fo0 + j];
    }
    __syncthreads();
    for (int i = tid; i < 64 * FI4; i += 128) {
        int node = i / FI4, c = i % FI4;
        int gn = n0 + node;
        float4 v = make_float4(0.f, 0.f, 0.f, 0.f);
        if (gn < n) {
            float4 r = *reinterpret_cast<const float4*>(hin + (size_t)gn * FI + c * 4);
            v.x = fmaxf(r.x + bs[c * 4 + 0], 0.f);
            v.y = fmaxf(r.y + bs[c * 4 + 1], 0.f);
            v.z = fmaxf(r.z + bs[c * 4 + 2], 0.f);
            v.w = fmaxf(r.w + bs[c * 4 + 3], 0.f);
        }
        hsT[(c * 4 + 0) * STR + node] = v.x;
        hsT[(c * 4 + 1) * STR + node] = v.y;
        hsT[(c * 4 + 2) * STR + node] = v.z;
        hsT[(c * 4 + 3) * STR + node] = v.w;
    }
    __syncthreads();

    const int fo_t = tid & 7;
    const int nd_t = tid >> 3;
    float acc[4][4] = {};
#pragma unroll 8
    for (int k = 0; k < FI; k++) {
        float4 w = *reinterpret_cast<const float4*>(Ws + k * 32 + fo_t * 4);
        float4 h = *reinterpret_cast<const float4*>(hsT + k * STR + nd_t * 4);
        acc[0][0] = fmaf(h.x, w.x, acc[0][0]);
        acc[0][1] = fmaf(h.x, w.y, acc[0][1]);
        acc[0][2] = fmaf(h.x, w.z, acc[0][2]);
        acc[0][3] = fmaf(h.x, w.w, acc[0][3]);
        acc[1][0] = fmaf(h.y, w.x, acc[1][0]);
        acc[1][1] = fmaf(h.y, w.y, acc[1][1]);
        acc[1][2] = fmaf(h.y, w.z, acc[1][2]);
        acc[1][3] = fmaf(h.y, w.w, acc[1][3]);
        acc[2][0] = fmaf(h.z, w.x, acc[2][0]);
        acc[2][1] = fmaf(h.z, w.y, acc[2][1]);
        acc[2][2] = fmaf(h.z, w.z, acc[2][2]);
        acc[2][3] = fmaf(h.z, w.w, acc[2][3]);
        acc[3][0] = fmaf(h.w, w.x, acc[3][0]);
        acc[3][1] = fmaf(h.w, w.y, acc[3][1]);
        acc[3][2] = fmaf(h.w, w.z, acc[3][2]);
        acc[3][3] = fmaf(h.w, w.w, acc[3][3]);
    }
#pragma unroll
    for (int i = 0; i < 4; i++) {
        int nd = n0 + nd_t * 4 + i;
        if (nd >= n) continue;
        size_t off = (size_t)nd * FO + fo0 + fo_t * 4;
        *reinterpret_cast<float4*>(tbuf + off) =
            make_float4(acc[i][0], acc[i][1], acc[i][2], acc[i][3]);
    }
}

// ---------------- warp-aligned gathers: out[dst] = d2*t[dst] + sum nm*t[src] --

// FO=96: one warp per dst, lanes 0..23 = feature chunks. CSR loads broadcast.
__global__ __launch_bounds__(256)
void k_gather96(const float* __restrict__ t, float* __restrict__ out, int n) {
    int w = blockIdx.x * 8 + (threadIdx.x >> 5);
    if (w >= n) return;
    int lane = threadIdx.x & 31;
    int r0 = g_off[w], r1 = g_off[w + 1];
    float d = g_deg[w];
    float d2 = d * d;
    if (lane >= 24) return;
    const size_t co = (size_t)lane * 4;
    float4 a = *reinterpret_cast<const float4*>(t + (size_t)w * 96 + co);
    a.x *= d2; a.y *= d2; a.z *= d2; a.w *= d2;
    int j = r0;
    for (; j + 1 < r1; j += 2) {
        int2 p0 = g_cpack[j], p1 = g_cpack[j + 1];
        float m0 = __int_as_float(p0.y), m1 = __int_as_float(p1.y);
        float4 v0 = *reinterpret_cast<const float4*>(t + (size_t)p0.x * 96 + co);
        float4 v1 = *reinterpret_cast<const float4*>(t + (size_t)p1.x * 96 + co);
        a.x = fmaf(m0, v0.x, a.x); a.y = fmaf(m0, v0.y, a.y);
        a.z = fmaf(m0, v0.z, a.z); a.w = fmaf(m0, v0.w, a.w);
        a.x = fmaf(m1, v1.x, a.x); a.y = fmaf(m1, v1.y, a.y);
        a.z = fmaf(m1, v1.z, a.z); a.w = fmaf(m1, v1.w, a.w);
    }
    if (j < r1) {
        int2 p0 = g_cpack[j];
        float m0 = __int_as_float(p0.y);
        float4 v0 = *reinterpret_cast<const float4*>(t + (size_t)p0.x * 96 + co);
        a.x = fmaf(m0, v0.x, a.x); a.y = fmaf(m0, v0.y, a.y);
        a.z = fmaf(m0, v0.z, a.z); a.w = fmaf(m0, v0.w, a.w);
    }
    *reinterpret_cast<float4*>(out + (size_t)w * 96 + co) = a;
}

// FO=64: one warp per dst; lanes = 16 feature chunks x 2 parallel edges.
__global__ __launch_bounds__(256)
void k_gather64(const float* __restrict__ t, float* __restrict__ out, int n) {
    int w = blockIdx.x * 8 + (threadIdx.x >> 5);
    if (w >= n) return;
    int lane = threadIdx.x & 31;
    int c = lane & 15;
    int eh = lane >> 4;        // 0,1
    int r0 = g_off[w], r1 = g_off[w + 1];
    const size_t co = (size_t)c * 4;
    float4 a = make_float4(0.f, 0.f, 0.f, 0.f);
    if (eh == 0) {
        float d = g_deg[w];
        float d2 = d * d;
        float4 sv = *reinterpret_cast<const float4*>(t + (size_t)w * 64 + co);
        a.x = d2 * sv.x; a.y = d2 * sv.y; a.z = d2 * sv.z; a.w = d2 * sv.w;
    }
    for (int j = r0 + eh; j < r1; j += 2) {
        int2 p = g_cpack[j];
        float m = __int_as_float(p.y);
        float4 v = *reinterpret_cast<const float4*>(t + (size_t)p.x * 64 + co);
        a.x = fmaf(m, v.x, a.x); a.y = fmaf(m, v.y, a.y);
        a.z = fmaf(m, v.z, a.z); a.w = fmaf(m, v.w, a.w);
    }
    a.x += __shfl_xor_sync(0xffffffffu, a.x, 16);
    a.y += __shfl_xor_sync(0xffffffffu, a.y, 16);
    a.z += __shfl_xor_sync(0xffffffffu, a.z, 16);
    a.w += __shfl_xor_sync(0xffffffffu, a.w, 16);
    if (eh == 0)
        *reinterpret_cast<float4*>(out + (size_t)w * 64 + co) = a;
}

// FO=32: one warp per dst; lanes = 8 feature chunks x 4 parallel edges.
__global__ __launch_bounds__(256)
void k_gather32(const float* __restrict__ t, float* __restrict__ out, int n) {
    int w = blockIdx.x * 8 + (threadIdx.x >> 5);
    if (w >= n) return;
    int lane = threadIdx.x & 31;
    int c = lane & 7;
    int eh = lane >> 3;        // 0..3
    int r0 = g_off[w], r1 = g_off[w + 1];
    const size_t co = (size_t)c * 4;
    float4 a = make_float4(0.f, 0.f, 0.f, 0.f);
    if (eh == 0) {
        float d = g_deg[w];
        float d2 = d * d;
        float4 sv = *reinterpret_cast<const float4*>(t + (size_t)w * 32 + co);
        a.x = d2 * sv.x; a.y = d2 * sv.y; a.z = d2 * sv.z; a.w = d2 * sv.w;
    }
    for (int j = r0 + eh; j < r1; j += 4) {
        int2 p = g_cpack[j];
        float m = __int_as_float(p.y);
        float4 v = *reinterpret_cast<const float4*>(t + (size_t)p.x * 32 + co);
        a.x = fmaf(m, v.x, a.x); a.y = fmaf(m, v.y, a.y);
        a.z = fmaf(m, v.z, a.z); a.w = fmaf(m, v.w, a.w);
    }
    a.x += __shfl_xor_sync(0xffffffffu, a.x, 8);
    a.y += __shfl_xor_sync(0xffffffffu, a.y, 8);
    a.z += __shfl_xor_sync(0xffffffffu, a.z, 8);
    a.w += __shfl_xor_sync(0xffffffffu, a.w, 8);
    a.x += __shfl_xor_sync(0xffffffffu, a.x, 16);
    a.y += __shfl_xor_sync(0xffffffffu, a.y, 16);
    a.z += __shfl_xor_sync(0xffffffffu, a.z, 16);
    a.w += __shfl_xor_sync(0xffffffffu, a.w, 16);
    if (eh == 0)
        *reinterpret_cast<float4*>(out + (size_t)w * 32 + co) = a;
}

// ---------------- pooling ----------------

// block (32,8), each block covers 2048 nodes; batch sorted -> running max
__global__ void k_pool(const float* __restrict__ h, const float* __restrict__ b4,
                       const void* __restrict__ batch, int n) {
    const int tx = threadIdx.x;   // feature lane
    const int ty = threadIdx.y;   // node row
    const int base = blockIdx.x * 2048;
    const float bb = __ldg(&b4[tx]);
    const int is64 = g_is64;
    const long long* b64 = (const long long*)batch;
    const int* b32 = (const int*)batch;
    float rmax = 0.f;
    int curg = -1;
    for (int off = ty; off < 2048; off += 8) {
        int nd = base + off;
        if (nd >= n) break;
        int g = is64 ? (int)b64[nd] : b32[nd];
        float v = fmaxf(h[(size_t)nd * 32 + tx] + bb, 0.f);
        if (g != curg) {
            if (curg >= 0)
                atomicMax(reinterpret_cast<int*>(&g_pool[curg * 32 + tx]),
                          __float_as_int(rmax));
            curg = g;
            rmax = v;
        } else {
            rmax = fmaxf(rmax, v);
        }
    }
    if (curg >= 0)
        atomicMax(reinterpret_cast<int*>(&g_pool[curg * 32 + tx]),
                  __float_as_int(rmax));
}

// ---------------- final MLP: relu(g@W5+b5)@W6+b6 ----------------

__global__ void k_mlp(const float* __restrict__ W5, const float* __restrict__ b5,
                      const float* __restrict__ W6, const float* __restrict__ b6,
                      float* __restrict__ out) {
    __shared__ float W5s[32 * 32], b5s[32], W6s[64], b6s[2];
    int t = threadIdx.x;   // 64 threads = 64 graphs
    for (int i = t; i < 1024; i += 64) W5s[i] = W5[i];
    if (t < 32) b5s[t] = b5[t];
    W6s[t] = W6[t];
    if (t < 2) b6s[t] = b6[t];
    __syncthreads();
    float p[32];
#pragma unroll
    for (int k = 0; k < 32; k++) p[k] = g_pool[t * 32 + k];
    float o0 = b6s[0], o1 = b6s[1];
#pragma unroll 4
    for (int j = 0; j < 32; j++) {
        float s = b5s[j];
#pragma unroll
        for (int k = 0; k < 32; k++) s = fmaf(p[k], W5s[k * 32 + j], s);
        s = fmaxf(s, 0.f);
        o0 = fmaf(s, W6s[j * 2], o0);
        o1 = fmaf(s, W6s[j * 2 + 1], o1);
    }
    out[t * 2] = o0;
    out[t * 2 + 1] = o1;
}

// ---------------- launch ----------------

extern "C" void kernel_launch(void* const* d_in, const int* in_sizes, int n_in,
                              void* d_out, int out_size) {
    const float* x  = (const float*)d_in[0];
    const void*  ei = d_in[1];
    const float* ew = (const float*)d_in[2];
    const void*  bt = d_in[3];
    const float* W1 = (const float*)d_in[4];
    const float* b1 = (const float*)d_in[5];
    const float* W2 = (const float*)d_in[6];
    const float* b2 = (const float*)d_in[7];
    const float* W3 = (const float*)d_in[8];
    const float* b3 = (const float*)d_in[9];
    const float* W4 = (const float*)d_in[10];
    const float* b4 = (const float*)d_in[11];
    const float* W5 = (const float*)d_in[12];
    const float* b5 = (const float*)d_in[13];
    const float* W6 = (const float*)d_in[14];
    const float* b6 = (const float*)d_in[15];
    float* out = (float*)d_out;

    const int n = in_sizes[0];
    const int e = in_sizes[2];

    const int nb  = (n + 255) / 256;
    const int ebk = (e + 255) / 256;
    const int nchunks = (n + 1023) / 1024;
    const int wgrid = (n + 7) / 8;        // warp-per-dst gathers

    k_init_detect<<<nb, 256>>>((const int*)ei, n);
    k_edges_pre<<<ebk, 256>>>(ei, ew, e);
    k_scan1<<<nchunks, 1024>>>(n);
    k_scan2<<<1, 1024>>>(nchunks);
    k_scan3_dis<<<nb, 256>>>(x, n);
    k_norm_fill<<<ebk, 256>>>(ew, x, e);

    const int gx = (n + 63) / 64;

    float* A; float* B; float* C;
    cudaGetSymbolAddress((void**)&A, g_A);
    cudaGetSymbolAddress((void**)&B, g_B);
    cudaGetSymbolAddress((void**)&C, g_C);

    // layer 2 (fused layer-1 expand): t2->B, gather -> C
    k_gemm2<<<dim3(gx, 3), 128>>>(W1, b1, W2, B, n);
    k_gather96<<<wgrid, 256>>>(B, C, n);

    // layer 3: in C (+b2,relu) -> t3->A, gather -> B
    k_gemm<96, 64><<<dim3(gx, 2), 128>>>(C, b2, W3, A, n);
    k_gather64<<<wgrid, 256>>>(A, B, n);

    // layer 4: in B (+b3,relu) -> t4->C, gather -> A
    k_gemm<64, 32><<<dim3(gx, 1), 128>>>(B, b3, W4, C, n);
    k_gather32<<<wgrid, 256>>>(C, A, n);

    // pool + MLP
    k_pool<<<(n + 2047) / 2048, dim3(32, 8)>>>(A, b4, bt, n);
    k_mlp<<<1, 64>>>(W5, b5, W6, b6, out);
}

// round 7
// speedup vs baseline: 1.0153x; 1.0153x over previous
#include <cuda_runtime.h>
#include <cstdint>

// ---------------------------------------------------------------------------
// GCN: 4 conv layers + global max pool + MLP.
// R6 resubmit (R6 bench was an infra failure; container died before running).
// R6: revert gathers/norm_fill to R4 form (int2-packed CSR), all GEMMs use
// Blackwell packed fma.rn.f32x2 (2 fp32 MACs/slot, exact fp32), staged smem
// with padded stride 68; layer-2 GEMM stages h1 from ax in-block with 2-way
// K-split weight reload to fit 48KB static smem.
// ---------------------------------------------------------------------------

constexpr int NN = 100000;
constexpr int EE = 1600000;
constexpr int GG = 64;

__device__ __align__(16) float g_deg[NN];            // deg, then dis (in place)
__device__ __align__(16) int   g_src[EE];
__device__ __align__(16) int   g_dst[EE];
__device__ __align__(16) int2  g_cpack[EE];          // CSR by dst: (src, norm bits)
__device__ __align__(16) int   g_off[NN + 1];
__device__ __align__(16) int   g_cnt[NN];
__device__ __align__(16) int   g_cur[NN];
__device__ __align__(16) int   g_aux[128];
__device__ __align__(16) float g_ax[NN];
__device__ __align__(16) float g_A[(size_t)NN * 128];
__device__ __align__(16) float g_B[(size_t)NN * 128];
__device__ __align__(16) float g_C[(size_t)NN * 128];
__device__ __align__(16) float g_pool[GG * 32];
__device__ int g_is64;

using u64 = unsigned long long;
__device__ __forceinline__ u64 pk2(float a, float b) {
    u64 r; asm("mov.b64 %0,{%1,%2};" : "=l"(r) : "f"(a), "f"(b)); return r;
}
__device__ __forceinline__ u64 ffma2(u64 a, u64 b, u64 c) {
    u64 d; asm("fma.rn.f32x2 %0,%1,%2,%3;" : "=l"(d) : "l"(a), "l"(b), "l"(c));
    return d;
}
__device__ __forceinline__ float2 up2(u64 v) {
    float2 r; asm("mov.b64 {%0,%1},%2;" : "=f"(r.x), "=f"(r.y) : "l"(v));
    return r;
}

// ---------------- init + dtype detect ----------------
// int64 node ids < 2^31 => every odd 32-bit word is 0. int32 => random ids.
__global__ void k_init_detect(const int* __restrict__ raw, int n) {
    int i = blockIdx.x * blockDim.x + threadIdx.x;
    if (i < n) {
        g_deg[i] = 1.0f;   // self loop weight
        g_cnt[i] = 0;
        g_cur[i] = 0;
    }
    if (blockIdx.x == 0) {
        __shared__ int any;
        if (threadIdx.x == 0) any = 0;
        __syncthreads();
        int v = 0;
        for (int k = threadIdx.x; k < 2048; k += blockDim.x) v |= raw[2 * k + 1];
        if (v) atomicOr(&any, 1);
        __syncthreads();
        if (threadIdx.x == 0) g_is64 = (any == 0) ? 1 : 0;
    }
}

__global__ void k_edges_pre(const void* __restrict__ ei,
                            const float* __restrict__ w, int e) {
    int i = blockIdx.x * blockDim.x + threadIdx.x;
    if (i >= e) return;
    int s, d;
    if (g_is64) {
        const long long* p = (const long long*)ei;
        s = (int)p[i];
        d = (int)p[(size_t)e + i];
    } else {
        const int* p = (const int*)ei;
        s = p[i];
        d = p[e + i];
    }
    g_src[i] = s;
    g_dst[i] = d;
    atomicAdd(&g_deg[d], w[i]);
    atomicAdd(&g_cnt[d], 1);
}

// ---------------- scan of g_cnt -> g_off ----------------

__global__ void k_scan1(int n) {   // 1024 threads/block, chunk=1024
    __shared__ int s[1024];
    int t = threadIdx.x;
    int base = blockIdx.x * 1024;
    int v = (base + t < n) ? g_cnt[base + t] : 0;
    s[t] = v;
    __syncthreads();
    for (int d = 1; d < 1024; d <<= 1) {
        int x = (t >= d) ? s[t - d] : 0;
        __syncthreads();
        s[t] += x;
        __syncthreads();
    }
    if (base + t < n) g_off[base + t + 1] = s[t];
    if (t == 1023) g_aux[blockIdx.x] = s[1023];
}

__global__ void k_scan2(int naux) {  // single block
    __shared__ int s[1024];
    int t = threadIdx.x;
    s[t] = (t < naux) ? g_aux[t] : 0;
    __syncthreads();
    for (int d = 1; d < 1024; d <<= 1) {
        int x = (t >= d) ? s[t - d] : 0;
        __syncthreads();
        s[t] += x;
        __syncthreads();
    }
    if (t < naux) g_aux[t] = (t > 0) ? s[t - 1] : 0;
}

// scan fixup + dis + pool zero
__global__ void k_scan3_dis(int n) {
    int i = blockIdx.x * blockDim.x + threadIdx.x;
    if (i < GG * 32) g_pool[i] = 0.f;
    if (i >= n) return;
    g_off[i + 1] += g_aux[i >> 10];
    if (i == 0) g_off[0] = 0;
    float dg = g_deg[i];
    g_deg[i] = (dg > 0.f) ? rsqrtf(dg) : 0.f;
}

// norm + CSR fill
__global__ void k_norm_fill(const float* __restrict__ w, int e) {
    int i = blockIdx.x * blockDim.x + threadIdx.x;
    if (i >= e) return;
    int s = g_src[i];
    int d = g_dst[i];
    float nm = g_deg[s] * w[i] * g_deg[d];
    int pos = g_off[d] + atomicAdd(&g_cur[d], 1);
    g_cpack[pos] = make_int2(s, __float_as_int(nm));
}

// ---------------- layer 1: gather x -> ax ----------------

__global__ void k_gather_ax(const float* __restrict__ x, int n) {
    int i = blockIdx.x * blockDim.x + threadIdx.x;
    if (i >= n) return;
    float d = g_deg[i];
    float acc = d * d * x[i];
    int r0 = g_off[i], r1 = g_off[i + 1];
    for (int j = r0; j < r1; j++) {
        int2 p = g_cpack[j];
        acc = fmaf(__int_as_float(p.y), x[p.x], acc);
    }
    g_ax[i] = acc;
}

// ---------------- packed-FMA main loop (shared by all GEMMs) ----------------
// hsT: [k][node] stride 68 (16B aligned, conflict-free). Ws: [k][32].
// Thread covers 4 nodes (as 2 packed pairs) x 4 fo.

#define GEMM_CORE(K0, K1, hsT, Ws)                                            \
    _Pragma("unroll 4")                                                       \
    for (int k = (K0); k < (K1); k++) {                                       \
        const u64* hp = reinterpret_cast<const u64*>(hsT + k * 68 + nd_t * 4);\
        u64 h01 = hp[0], h23 = hp[1];                                         \
        float4 w = *reinterpret_cast<const float4*>(Ws + (k - (K0)) * 32 + fo_t * 4); \
        u64 w0 = pk2(w.x, w.x), w1 = pk2(w.y, w.y);                           \
        u64 w2 = pk2(w.z, w.z), w3 = pk2(w.w, w.w);                           \
        acc[0][0] = ffma2(h01, w0, acc[0][0]);                                \
        acc[0][1] = ffma2(h01, w1, acc[0][1]);                                \
        acc[0][2] = ffma2(h01, w2, acc[0][2]);                                \
        acc[0][3] = ffma2(h01, w3, acc[0][3]);                                \
        acc[1][0] = ffma2(h23, w0, acc[1][0]);                                \
        acc[1][1] = ffma2(h23, w1, acc[1][1]);                                \
        acc[1][2] = ffma2(h23, w2, acc[1][2]);                                \
        acc[1][3] = ffma2(h23, w3, acc[1][3]);                                \
    }

#define GEMM_STORE(FO, tbuf)                                                  \
    _Pragma("unroll")                                                         \
    for (int p = 0; p < 2; p++) {                                             \
        float2 c0 = up2(acc[p][0]), c1 = up2(acc[p][1]);                      \
        float2 c2 = up2(acc[p][2]), c3 = up2(acc[p][3]);                      \
        int nd = n0 + nd_t * 4 + 2 * p;                                       \
        if (nd < n)                                                           \
            *reinterpret_cast<float4*>(tbuf + (size_t)nd * FO + fo0 + fo_t * 4) = \
                make_float4(c0.x, c1.x, c2.x, c3.x);                          \
        if (nd + 1 < n)                                                       \
            *reinterpret_cast<float4*>(tbuf + (size_t)(nd + 1) * FO + fo0 + fo_t * 4) = \
                make_float4(c0.y, c1.y, c2.y, c3.y);                          \
    }

// ---------------- layer 2 GEMM (fused layer-1 expand): FI=128, FO=96 --------
// h1[node][k] = relu(ax[node]*W1[k] + b1[k]) staged in-block; K split in 2.

__global__ __launch_bounds__(128)
void k_gemm2(const float* __restrict__ W1, const float* __restrict__ b1,
             const float* __restrict__ W2,
             float* __restrict__ tbuf, int n) {
    __shared__ __align__(16) float hsT[128 * 68];
    __shared__ __align__(16) float Ws[64 * 32];
    __shared__ __align__(16) float W1s[128], b1s[128], axs[64];
    const int tid = threadIdx.x;
    const int fo0 = blockIdx.y * 32;
    const int n0 = blockIdx.x * 64;

    W1s[tid] = W1[tid];
    b1s[tid] = b1[tid];
    if (tid < 64) {
        int nd = n0 + tid;
        axs[tid] = (nd < n) ? g_ax[nd] : 0.f;
    }
    __syncthreads();

    // stage h1: thread handles node = tid&63, k = (tid>>6) + 2m
    {
        int node = tid & 63;
        float ax = axs[node];
#pragma unroll 8
        for (int m = 0; m < 64; m++) {
            int k = (tid >> 6) + 2 * m;
            hsT[k * 68 + node] = fmaxf(fmaf(ax, W1s[k], b1s[k]), 0.f);
        }
    }

    const int fo_t = tid & 7;
    const int nd_t = tid >> 3;
    u64 acc[2][4] = {};

#pragma unroll
    for (int half = 0; half < 2; half++) {
        __syncthreads();
        for (int i = tid; i < 64 * 32; i += 128) {
            int kl = i >> 5, j = i & 31;
            Ws[i] = W2[(half * 64 + kl) * 96 + fo0 + j];
        }
        __syncthreads();
        GEMM_CORE(half * 64, half * 64 + 64, hsT, Ws)
    }
    GEMM_STORE(96, tbuf)
}

// ---------------- generic GEMM layers 3,4: relu(in+bias) @ W ----------------

template <int FI, int FO>
__global__ __launch_bounds__(128)
void k_gemm(const float* __restrict__ hin, const float* __restrict__ bin,
            const float* __restrict__ W,
            float* __restrict__ tbuf, int n) {
    constexpr int FI4 = FI / 4;
    __shared__ __align__(16) float hsT[FI * 68];
    __shared__ __align__(16) float Ws[FI * 32];
    __shared__ __align__(16) float bs[FI];
    const int tid = threadIdx.x;
    const int fo0 = blockIdx.y * 32;
    const int n0 = blockIdx.x * 64;

    for (int i = tid; i < FI; i += 128) bs[i] = bin[i];
    for (int i = tid; i < FI * 32; i += 128) {
        int k = i >> 5, j = i & 31;
        Ws[i] = W[k * FO + fo0 + j];
    }
    __syncthreads();
    for (int i = tid; i < 64 * FI4; i += 128) {
        int node = i / FI4, c = i % FI4;
        int gn = n0 + node;
        float4 v = make_float4(0.f, 0.f, 0.f, 0.f);
        if (gn < n) {
            float4 r = *reinterpret_cast<const float4*>(hin + (size_t)gn * FI + c * 4);
            v.x = fmaxf(r.x + bs[c * 4 + 0], 0.f);
            v.y = fmaxf(r.y + bs[c * 4 + 1], 0.f);
            v.z = fmaxf(r.z + bs[c * 4 + 2], 0.f);
            v.w = fmaxf(r.w + bs[c * 4 + 3], 0.f);
        }
        hsT[(c * 4 + 0) * 68 + node] = v.x;
        hsT[(c * 4 + 1) * 68 + node] = v.y;
        hsT[(c * 4 + 2) * 68 + node] = v.z;
        hsT[(c * 4 + 3) * 68 + node] = v.w;
    }
    __syncthreads();

    const int fo_t = tid & 7;
    const int nd_t = tid >> 3;
    u64 acc[2][4] = {};
    GEMM_CORE(0, FI, hsT, Ws)
    GEMM_STORE(FO, tbuf)
}

// ---------------- per-dst gather: out[dst] = d2*t[dst] + sum nm*t[src] ------
// R4 mapping: thread = (dst, 4-feature chunk). int2-packed CSR.

template <int FO>
__global__ __launch_bounds__(256)
void k_gather(const float* __restrict__ t, float* __restrict__ out, int n) {
    constexpr int FO4 = FO / 4;
    int idx = blockIdx.x * 256 + threadIdx.x;
    if (idx >= n * FO4) return;
    int dst = idx / FO4;
    int c = idx - dst * FO4;
    const int r0 = g_off[dst], r1 = g_off[dst + 1];
    float d = g_deg[dst];
    float d2 = d * d;
    const size_t co = (size_t)c * 4;
    float4 a = *reinterpret_cast<const float4*>(t + (size_t)dst * FO + co);
    a.x *= d2; a.y *= d2; a.z *= d2; a.w *= d2;
    int j = r0;
    for (; j + 1 < r1; j += 2) {
        int2 p0 = g_cpack[j], p1 = g_cpack[j + 1];
        float m0 = __int_as_float(p0.y), m1 = __int_as_float(p1.y);
        float4 v0 = *reinterpret_cast<const float4*>(t + (size_t)p0.x * FO + co);
        float4 v1 = *reinterpret_cast<const float4*>(t + (size_t)p1.x * FO + co);
        a.x = fmaf(m0, v0.x, a.x); a.y = fmaf(m0, v0.y, a.y);
        a.z = fmaf(m0, v0.z, a.z); a.w = fmaf(m0, v0.w, a.w);
        a.x = fmaf(m1, v1.x, a.x); a.y = fmaf(m1, v1.y, a.y);
        a.z = fmaf(m1, v1.z, a.z); a.w = fmaf(m1, v1.w, a.w);
    }
    if (j < r1) {
        int2 p0 = g_cpack[j];
        float m0 = __int_as_float(p0.y);
        float4 v0 = *reinterpret_cast<const float4*>(t + (size_t)p0.x * FO + co);
        a.x = fmaf(m0, v0.x, a.x); a.y = fmaf(m0, v0.y, a.y);
        a.z = fmaf(m0, v0.z, a.z); a.w = fmaf(m0, v0.w, a.w);
    }
    *reinterpret_cast<float4*>(out + (size_t)dst * FO + co) = a;
}

// ---------------- pooling ----------------

// block (32,8), each block covers 2048 nodes; batch sorted -> running max
__global__ void k_pool(const float* __restrict__ h, const float* __restrict__ b4,
                       const void* __restrict__ batch, int n) {
    const int tx = threadIdx.x;   // feature lane
    const int ty = threadIdx.y;   // node row
    const int base = blockIdx.x * 2048;
    const float bb = __ldg(&b4[tx]);
    const int is64 = g_is64;
    const long long* b64 = (const long long*)batch;
    const int* b32 = (const int*)batch;
    float rmax = 0.f;
    int curg = -1;
    for (int off = ty; off < 2048; off += 8) {
        int nd = base + off;
        if (nd >= n) break;
        int g = is64 ? (int)b64[nd] : b32[nd];
        float v = fmaxf(h[(size_t)nd * 32 + tx] + bb, 0.f);
        if (g != curg) {
            if (curg >= 0)
                atomicMax(reinterpret_cast<int*>(&g_pool[curg * 32 + tx]),
                          __float_as_int(rmax));
            curg = g;
            rmax = v;
        } else {
            rmax = fmaxf(rmax, v);
        }
    }
    if (curg >= 0)
        atomicMax(reinterpret_cast<int*>(&g_pool[curg * 32 + tx]),
                  __float_as_int(rmax));
}

// ---------------- final MLP: relu(g@W5+b5)@W6+b6 ----------------

__global__ void k_mlp(const float* __restrict__ W5, const float* __restrict__ b5,
                      const float* __restrict__ W6, const float* __restrict__ b6,
                      float* __restrict__ out) {
    __shared__ float W5s[32 * 32], b5s[32], W6s[64], b6s[2];
    int t = threadIdx.x;   // 64 threads = 64 graphs
    for (int i = t; i < 1024; i += 64) W5s[i] = W5[i];
    if (t < 32) b5s[t] = b5[t];
    W6s[t] = W6[t];
    if (t < 2) b6s[t] = b6[t];
    __syncthreads();
    float p[32];
#pragma unroll
    for (int k = 0; k < 32; k++) p[k] = g_pool[t * 32 + k];
    float o0 = b6s[0], o1 = b6s[1];
#pragma unroll 4
    for (int j = 0; j < 32; j++) {
        float s = b5s[j];
#pragma unroll
        for (int k = 0; k < 32; k++) s = fmaf(p[k], W5s[k * 32 + j], s);
        s = fmaxf(s, 0.f);
        o0 = fmaf(s, W6s[j * 2], o0);
        o1 = fmaf(s, W6s[j * 2 + 1], o1);
    }
    out[t * 2] = o0;
    out[t * 2 + 1] = o1;
}

// ---------------- launch ----------------

extern "C" void kernel_launch(void* const* d_in, const int* in_sizes, int n_in,
                              void* d_out, int out_size) {
    const float* x  = (const float*)d_in[0];
    const void*  ei = d_in[1];
    const float* ew = (const float*)d_in[2];
    const void*  bt = d_in[3];
    const float* W1 = (const float*)d_in[4];
    const float* b1 = (const float*)d_in[5];
    const float* W2 = (const float*)d_in[6];
    const float* b2 = (const float*)d_in[7];
    const float* W3 = (const float*)d_in[8];
    const float* b3 = (const float*)d_in[9];
    const float* W4 = (const float*)d_in[10];
    const float* b4 = (const float*)d_in[11];
    const float* W5 = (const float*)d_in[12];
    const float* b5 = (const float*)d_in[13];
    const float* W6 = (const float*)d_in[14];
    const float* b6 = (const float*)d_in[15];
    float* out = (float*)d_out;

    const int n = in_sizes[0];
    const int e = in_sizes[2];

    const int nb  = (n + 255) / 256;
    const int ebk = (e + 255) / 256;
    const int nchunks = (n + 1023) / 1024;

    k_init_detect<<<nb, 256>>>((const int*)ei, n);
    k_edges_pre<<<ebk, 256>>>(ei, ew, e);
    k_scan1<<<nchunks, 1024>>>(n);
    k_scan2<<<1, 1024>>>(nchunks);
    k_scan3_dis<<<nb, 256>>>(n);
    k_norm_fill<<<ebk, 256>>>(ew, e);
    k_gather_ax<<<nb, 256>>>(x, n);

    const int gx = (n + 63) / 64;

    float* A; float* B; float* C;
    cudaGetSymbolAddress((void**)&A, g_A);
    cudaGetSymbolAddress((void**)&B, g_B);
    cudaGetSymbolAddress((void**)&C, g_C);

    // layer 2 (fused layer-1 expand): t2->B, gather -> C
    k_gemm2<<<dim3(gx, 3), 128>>>(W1, b1, W2, B, n);
    k_gather<96><<<(n * 24 + 255) / 256, 256>>>(B, C, n);

    // layer 3: in C (+b2,relu) -> t3->A, gather -> B
    k_gemm<96, 64><<<dim3(gx, 2), 128>>>(C, b2, W3, A, n);
    k_gather<64><<<(n * 16 + 255) / 256, 256>>>(A, B, n);

    // layer 4: in B (+b3,relu) -> t4->C, gather -> A
    k_gemm<64, 32><<<dim3(gx, 1), 128>>>(B, b3, W4, C, n);
    k_gather<32><<<(n * 8 + 255) / 256, 256>>>(C, A, n);

    // pool + MLP
    k_pool<<<(n + 2047) / 2048, dim3(32, 8)>>>(A, b4, bt, n);
    k_mlp<<<1, 64>>>(W5, b5, W6, b6, out);
}

// round 10
// speedup vs baseline: 1.1158x; 1.0989x over previous
#include <cuda_runtime.h>
#include <cuda_fp16.h>
#include <cstdint>

// ---------------------------------------------------------------------------
// GCN: 4 conv layers + global max pool + MLP.  (R10 = third submit of R8)
// R4 structure (proven 454.7us) + fp16 inter-layer h-buffers (halves the
// L2-bound gather traffic). fp32 accumulation everywhere; only storage is fp16.
// ---------------------------------------------------------------------------

constexpr int NN = 100000;
constexpr int EE = 1600000;
constexpr int GG = 64;

__device__ __align__(16) float g_deg[NN];            // deg, then dis (in place)
__device__ __align__(16) int   g_src[EE];
__device__ __align__(16) int   g_dst[EE];
__device__ __align__(16) int2  g_cpack[EE];          // CSR by dst: (src, norm bits)
__device__ __align__(16) int   g_off[NN + 1];
__device__ __align__(16) int   g_cnt[NN];
__device__ __align__(16) int   g_cur[NN];
__device__ __align__(16) int   g_aux[128];
__device__ __align__(16) float g_ax[NN];
__device__ __align__(16) __half g_A[(size_t)NN * 128];
__device__ __align__(16) __half g_B[(size_t)NN * 128];
__device__ __align__(16) __half g_C[(size_t)NN * 128];
__device__ __align__(16) float g_pool[GG * 32];
__device__ int g_is64;

struct __align__(8) h4 { __half2 a, b; };   // 4 halves, one 8B access

__device__ __forceinline__ float4 h4_to_f4(h4 v) {
    float2 f0 = __half22float2(v.a);
    float2 f1 = __half22float2(v.b);
    return make_float4(f0.x, f0.y, f1.x, f1.y);
}
__device__ __forceinline__ h4 f4_to_h4(float4 v) {
    h4 r;
    r.a = __floats2half2_rn(v.x, v.y);
    r.b = __floats2half2_rn(v.z, v.w);
    return r;
}

// ---------------- init + dtype detect ----------------
// int64 node ids < 2^31 => every odd 32-bit word is 0. int32 => random ids.
__global__ void k_init_detect(const int* __restrict__ raw, int n) {
    int i = blockIdx.x * blockDim.x + threadIdx.x;
    if (i < n) {
        g_deg[i] = 1.0f;   // self loop weight
        g_cnt[i] = 0;
        g_cur[i] = 0;
    }
    if (blockIdx.x == 0) {
        __shared__ int any;
        if (threadIdx.x == 0) any = 0;
        __syncthreads();
        int v = 0;
        for (int k = threadIdx.x; k < 2048; k += blockDim.x) v |= raw[2 * k + 1];
        if (v) atomicOr(&any, 1);
        __syncthreads();
        if (threadIdx.x == 0) g_is64 = (any == 0) ? 1 : 0;
    }
}

__global__ void k_edges_pre(const void* __restrict__ ei,
                            const float* __restrict__ w, int e) {
    int i = blockIdx.x * blockDim.x + threadIdx.x;
    if (i >= e) return;
    int s, d;
    if (g_is64) {
        const long long* p = (const long long*)ei;
        s = (int)p[i];
        d = (int)p[(size_t)e + i];
    } else {
        const int* p = (const int*)ei;
        s = p[i];
        d = p[e + i];
    }
    g_src[i] = s;
    g_dst[i] = d;
    atomicAdd(&g_deg[d], w[i]);
    atomicAdd(&g_cnt[d], 1);
}

// ---------------- scan of g_cnt -> g_off ----------------

__global__ void k_scan1(int n) {   // 1024 threads/block, chunk=1024
    __shared__ int s[1024];
    int t = threadIdx.x;
    int base = blockIdx.x * 1024;
    int v = (base + t < n) ? g_cnt[base + t] : 0;
    s[t] = v;
    __syncthreads();
    for (int d = 1; d < 1024; d <<= 1) {
        int x = (t >= d) ? s[t - d] : 0;
        __syncthreads();
        s[t] += x;
        __syncthreads();
    }
    if (base + t < n) g_off[base + t + 1] = s[t];
    if (t == 1023) g_aux[blockIdx.x] = s[1023];
}

__global__ void k_scan2(int naux) {  // single block
    __shared__ int s[1024];
    int t = threadIdx.x;
    s[t] = (t < naux) ? g_aux[t] : 0;
    __syncthreads();
    for (int d = 1; d < 1024; d <<= 1) {
        int x = (t >= d) ? s[t - d] : 0;
        __syncthreads();
        s[t] += x;
        __syncthreads();
    }
    if (t < naux) g_aux[t] = (t > 0) ? s[t - 1] : 0;
}

// scan fixup + dis + pool zero
__global__ void k_scan3_dis(int n) {
    int i = blockIdx.x * blockDim.x + threadIdx.x;
    if (i < GG * 32) g_pool[i] = 0.f;
    if (i >= n) return;
    g_off[i + 1] += g_aux[i >> 10];
    if (i == 0) g_off[0] = 0;
    float dg = g_deg[i];
    g_deg[i] = (dg > 0.f) ? rsqrtf(dg) : 0.f;
}

// norm + CSR fill
__global__ void k_norm_fill(const float* __restrict__ w, int e) {
    int i = blockIdx.x * blockDim.x + threadIdx.x;
    if (i >= e) return;
    int s = g_src[i];
    int d = g_dst[i];
    float nm = g_deg[s] * w[i] * g_deg[d];
    int pos = g_off[d] + atomicAdd(&g_cur[d], 1);
    g_cpack[pos] = make_int2(s, __float_as_int(nm));
}

// ---------------- layer 1: gather x -> ax (fp32) ----------------

__global__ void k_gather_ax(const float* __restrict__ x, int n) {
    int i = blockIdx.x * blockDim.x + threadIdx.x;
    if (i >= n) return;
    float d = g_deg[i];
    float acc = d * d * x[i];
    int r0 = g_off[i], r1 = g_off[i + 1];
    for (int j = r0; j < r1; j++) {
        int2 p = g_cpack[j];
        acc = fmaf(__int_as_float(p.y), x[p.x], acc);
    }
    g_ax[i] = acc;
}

// ---------------- layer 2 GEMM (fused layer-1 expand): FI=128, FO=96 --------
// h1[node][k] = relu(ax[node]*W1[k] + b1[k]) computed on the fly.

__global__ __launch_bounds__(128)
void k_gemm2(const float* __restrict__ W1, const float* __restrict__ b1,
             const float* __restrict__ W2,
             __half* __restrict__ tbuf, int n) {
    __shared__ __align__(16) float W1s[128];
    __shared__ __align__(16) float b1s[128];
    __shared__ __align__(16) float Ws[128 * 32];
    const int tid = threadIdx.x;
    const int fo0 = blockIdx.y * 32;
    const int n0 = blockIdx.x * 64;

    W1s[tid] = W1[tid];
    b1s[tid] = b1[tid];
    for (int i = tid; i < 128 * 32; i += 128) {
        int k = i >> 5, j = i & 31;
        Ws[i] = W2[k * 96 + fo0 + j];
    }
    const int fo_t = tid & 7;     // 8 groups of 4 fo
    const int nd_t = tid >> 3;    // 16 groups of 4 nodes
    float axv[4];
#pragma unroll
    for (int i = 0; i < 4; i++) {
        int nd = n0 + nd_t * 4 + i;
        axv[i] = (nd < n) ? g_ax[nd] : 0.f;
    }
    __syncthreads();

    float acc[4][4] = {};
#pragma unroll 8
    for (int k = 0; k < 128; k++) {
        float w1 = W1s[k], bb = b1s[k];
        float4 w = *reinterpret_cast<const float4*>(Ws + k * 32 + fo_t * 4);
#pragma unroll
        for (int i = 0; i < 4; i++) {
            float h = fmaxf(fmaf(axv[i], w1, bb), 0.f);
            acc[i][0] = fmaf(h, w.x, acc[i][0]);
            acc[i][1] = fmaf(h, w.y, acc[i][1]);
            acc[i][2] = fmaf(h, w.z, acc[i][2]);
            acc[i][3] = fmaf(h, w.w, acc[i][3]);
        }
    }
#pragma unroll
    for (int i = 0; i < 4; i++) {
        int nd = n0 + nd_t * 4 + i;
        if (nd >= n) continue;
        size_t off = (size_t)nd * 96 + fo0 + fo_t * 4;
        *reinterpret_cast<h4*>(tbuf + off) =
            f4_to_h4(make_float4(acc[i][0], acc[i][1], acc[i][2], acc[i][3]));
    }
}

// ---------------- generic GEMM layers 3,4: relu(in+bias) @ W ----------------

template <int FI, int FO>
__global__ __launch_bounds__(128)
void k_gemm(const __half* __restrict__ hin, const float* __restrict__ bin,
            const float* __restrict__ W,
            __half* __restrict__ tbuf, int n) {
    constexpr int FI4 = FI / 4;
    __shared__ __align__(16) float hsT[FI * 65];      // [k][node], stride 65
    __shared__ __align__(16) float Ws[FI * 32];
    __shared__ __align__(16) float bs[FI];
    const int tid = threadIdx.x;
    const int fo0 = blockIdx.y * 32;
    const int n0 = blockIdx.x * 64;

    for (int i = tid; i < FI; i += 128) bs[i] = bin[i];
    for (int i = tid; i < FI * 32; i += 128) {
        int k = i >> 5, j = i & 31;
        Ws[i] = W[k * FO + fo0 + j];
    }
    __syncthreads();
    for (int i = tid; i < 64 * FI4; i += 128) {
        int node = i / FI4, c = i % FI4;
        int gn = n0 + node;
        float4 v = make_float4(0.f, 0.f, 0.f, 0.f);
        if (gn < n) {
            float4 r = h4_to_f4(*reinterpret_cast<const h4*>(hin + (size_t)gn * FI + c * 4));
            v.x = fmaxf(r.x + bs[c * 4 + 0], 0.f);
            v.y = fmaxf(r.y + bs[c * 4 + 1], 0.f);
            v.z = fmaxf(r.z + bs[c * 4 + 2], 0.f);
            v.w = fmaxf(r.w + bs[c * 4 + 3], 0.f);
        }
        hsT[(c * 4 + 0) * 65 + node] = v.x;
        hsT[(c * 4 + 1) * 65 + node] = v.y;
        hsT[(c * 4 + 2) * 65 + node] = v.z;
        hsT[(c * 4 + 3) * 65 + node] = v.w;
    }
    __syncthreads();

    const int fo_t = tid & 7;
    const int nd_t = tid >> 3;
    float acc[4][4] = {};
#pragma unroll 8
    for (int k = 0; k < FI; k++) {
        float4 w = *reinterpret_cast<const float4*>(Ws + k * 32 + fo_t * 4);
        const float* hr = hsT + k * 65 + nd_t * 4;
#pragma unroll
        for (int i = 0; i < 4; i++) {
            float h = hr[i];
            acc[i][0] = fmaf(h, w.x, acc[i][0]);
            acc[i][1] = fmaf(h, w.y, acc[i][1]);
            acc[i][2] = fmaf(h, w.z, acc[i][2]);
            acc[i][3] = fmaf(h, w.w, acc[i][3]);
        }
    }
#pragma unroll
    for (int i = 0; i < 4; i++) {
        int nd = n0 + nd_t * 4 + i;
        if (nd >= n) continue;
        size_t off = (size_t)nd * FO + fo0 + fo_t * 4;
        *reinterpret_cast<h4*>(tbuf + off) =
            f4_to_h4(make_float4(acc[i][0], acc[i][1], acc[i][2], acc[i][3]));
    }
}

// ---------------- per-dst gather: out[dst] = d2*t[dst] + sum nm*t[src] ------
// Thread = (dst, 4-feature chunk). fp16 loads/stores, fp32 accumulate.

template <int FO>
__global__ __launch_bounds__(256)
void k_gather(const __half* __restrict__ t, __half* __restrict__ out, int n) {
    constexpr int FO4 = FO / 4;
    int idx = blockIdx.x * 256 + threadIdx.x;
    if (idx >= n * FO4) return;
    int dst = idx / FO4;
    int c = idx - dst * FO4;
    const int r0 = g_off[dst], r1 = g_off[dst + 1];
    float d = g_deg[dst];
    float d2 = d * d;
    const size_t co = (size_t)c * 4;
    float4 a = h4_to_f4(*reinterpret_cast<const h4*>(t + (size_t)dst * FO + co));
    a.x *= d2; a.y *= d2; a.z *= d2; a.w *= d2;
    int j = r0;
    for (; j + 1 < r1; j += 2) {
        int2 p0 = g_cpack[j], p1 = g_cpack[j + 1];
        float m0 = __int_as_float(p0.y), m1 = __int_as_float(p1.y);
        float4 v0 = h4_to_f4(*reinterpret_cast<const h4*>(t + (size_t)p0.x * FO + co));
        float4 v1 = h4_to_f4(*reinterpret_cast<const h4*>(t + (size_t)p1.x * FO + co));
        a.x = fmaf(m0, v0.x, a.x); a.y = fmaf(m0, v0.y, a.y);
        a.z = fmaf(m0, v0.z, a.z); a.w = fmaf(m0, v0.w, a.w);
        a.x = fmaf(m1, v1.x, a.x); a.y = fmaf(m1, v1.y, a.y);
        a.z = fmaf(m1, v1.z, a.z); a.w = fmaf(m1, v1.w, a.w);
    }
    if (j < r1) {
        int2 p0 = g_cpack[j];
        float m0 = __int_as_float(p0.y);
        float4 v0 = h4_to_f4(*reinterpret_cast<const h4*>(t + (size_t)p0.x * FO + co));
        a.x = fmaf(m0, v0.x, a.x); a.y = fmaf(m0, v0.y, a.y);
        a.z = fmaf(m0, v0.z, a.z); a.w = fmaf(m0, v0.w, a.w);
    }
    *reinterpret_cast<h4*>(out + (size_t)dst * FO + co) = f4_to_h4(a);
}

// ---------------- pooling ----------------

// block (32,8), each block covers 2048 nodes; batch sorted -> running max
__global__ void k_pool(const __half* __restrict__ h, const float* __restrict__ b4,
                       const void* __restrict__ batch, int n) {
    const int tx = threadIdx.x;   // feature lane
    const int ty = threadIdx.y;   // node row
    const int base = blockIdx.x * 2048;
    const float bb = __ldg(&b4[tx]);
    const int is64 = g_is64;
    const long long* b64 = (const long long*)batch;
    const int* b32 = (const int*)batch;
    float rmax = 0.f;
    int curg = -1;
    for (int off = ty; off < 2048; off += 8) {
        int nd = base + off;
        if (nd >= n) break;
        int g = is64 ? (int)b64[nd] : b32[nd];
        float v = fmaxf(__half2float(h[(size_t)nd * 32 + tx]) + bb, 0.f);
        if (g != curg) {
            if (curg >= 0)
                atomicMax(reinterpret_cast<int*>(&g_pool[curg * 32 + tx]),
                          __float_as_int(rmax));
            curg = g;
            rmax = v;
        } else {
            rmax = fmaxf(rmax, v);
        }
    }
    if (curg >= 0)
        atomicMax(reinterpret_cast<int*>(&g_pool[curg * 32 + tx]),
                  __float_as_int(rmax));
}

// ---------------- final MLP: relu(g@W5+b5)@W6+b6 ----------------

__global__ void k_mlp(const float* __restrict__ W5, const float* __restrict__ b5,
                      const float* __restrict__ W6, const float* __restrict__ b6,
                      float* __restrict__ out) {
    __shared__ float W5s[32 * 32], b5s[32], W6s[64], b6s[2];
    int t = threadIdx.x;   // 64 threads = 64 graphs
    for (int i = t; i < 1024; i += 64) W5s[i] = W5[i];
    if (t < 32) b5s[t] = b5[t];
    W6s[t] = W6[t];
    if (t < 2) b6s[t] = b6[t];
    __syncthreads();
    float p[32];
#pragma unroll
    for (int k = 0; k < 32; k++) p[k] = g_pool[t * 32 + k];
    float o0 = b6s[0], o1 = b6s[1];
#pragma unroll 4
    for (int j = 0; j < 32; j++) {
        float s = b5s[j];
#pragma unroll
        for (int k = 0; k < 32; k++) s = fmaf(p[k], W5s[k * 32 + j], s);
        s = fmaxf(s, 0.f);
        o0 = fmaf(s, W6s[j * 2], o0);
        o1 = fmaf(s, W6s[j * 2 + 1], o1);
    }
    out[t * 2] = o0;
    out[t * 2 + 1] = o1;
}

// ---------------- launch ----------------

extern "C" void kernel_launch(void* const* d_in, const int* in_sizes, int n_in,
                              void* d_out, int out_size) {
    const float* x  = (const float*)d_in[0];
    const void*  ei = d_in[1];
    const float* ew = (const float*)d_in[2];
    const void*  bt = d_in[3];
    const float* W1 = (const float*)d_in[4];
    const float* b1 = (const float*)d_in[5];
    const float* W2 = (const float*)d_in[6];
    const float* b2 = (const float*)d_in[7];
    const float* W3 = (const float*)d_in[8];
    const float* b3 = (const float*)d_in[9];
    const float* W4 = (const float*)d_in[10];
    const float* b4 = (const float*)d_in[11];
    const float* W5 = (const float*)d_in[12];
    const float* b5 = (const float*)d_in[13];
    const float* W6 = (const float*)d_in[14];
    const float* b6 = (const float*)d_in[15];
    float* out = (float*)d_out;

    const int n = in_sizes[0];
    const int e = in_sizes[2];

    const int nb  = (n + 255) / 256;
    const int ebk = (e + 255) / 256;
    const int nchunks = (n + 1023) / 1024;

    k_init_detect<<<nb, 256>>>((const int*)ei, n);
    k_edges_pre<<<ebk, 256>>>(ei, ew, e);
    k_scan1<<<nchunks, 1024>>>(n);
    k_scan2<<<1, 1024>>>(nchunks);
    k_scan3_dis<<<nb, 256>>>(n);
    k_norm_fill<<<ebk, 256>>>(ew, e);
    k_gather_ax<<<nb, 256>>>(x, n);

    const int gx = (n + 63) / 64;

    __half* A; __half* B; __half* C;
    cudaGetSymbolAddress((void**)&A, g_A);
    cudaGetSymbolAddress((void**)&B, g_B);
    cudaGetSymbolAddress((void**)&C, g_C);

    // layer 2 (fused layer-1 expand): t2->B, gather -> C
    k_gemm2<<<dim3(gx, 3), 128>>>(W1, b1, W2, B, n);
    k_gather<96><<<(n * 24 + 255) / 256, 256>>>(B, C, n);

    // layer 3: in C (+b2,relu) -> t3->A, gather -> B
    k_gemm<96, 64><<<dim3(gx, 2), 128>>>(C, b2, W3, A, n);
    k_gather<64><<<(n * 16 + 255) / 256, 256>>>(A, B, n);

    // layer 4: in B (+b3,relu) -> t4->C, gather -> A
    k_gemm<64, 32><<<dim3(gx, 1), 128>>>(B, b3, W4, C, n);
    k_gather<32><<<(n * 8 + 255) / 256, 256>>>(C, A, n);

    // pool + MLP
    k_pool<<<(n + 2047) / 2048, dim3(32, 8)>>>(A, b4, bt, n);
    k_mlp<<<1, 64>>>(W5, b5, W6, b6, out);
}

// round 12
// speedup vs baseline: 1.1781x; 1.0559x over previous
#include <cuda_runtime.h>
#include <cuda_fp16.h>
#include <mma.h>
#include <cstdint>

using namespace nvcuda;

// ---------------------------------------------------------------------------
// GCN: 4 conv layers + global max pool + MLP.
// R12 = resubmit of R11 (container infra failure; source audited, unchanged).
// R11 = R10 (426us: fp16 h-buffers, CSR gathers) + tensor-core GEMMs:
// wmma m16n16k16 fp16-in/fp32-accum, weights fp16 in smem, bias+relu fused
// into A staging, layer-2 GEMM stages h1 from ax in-block.
// ---------------------------------------------------------------------------

constexpr int NN = 100000;
constexpr int EE = 1600000;
constexpr int GG = 64;

__device__ __align__(16) float g_deg[NN];            // deg, then dis (in place)
__device__ __align__(16) int   g_src[EE];
__device__ __align__(16) int   g_dst[EE];
__device__ __align__(16) int2  g_cpack[EE];          // CSR by dst: (src, norm bits)
__device__ __align__(16) int   g_off[NN + 1];
__device__ __align__(16) int   g_cnt[NN];
__device__ __align__(16) int   g_cur[NN];
__device__ __align__(16) int   g_aux[128];
__device__ __align__(16) float g_ax[NN];
__device__ __align__(16) __half g_A[(size_t)NN * 128];
__device__ __align__(16) __half g_B[(size_t)NN * 128];
__device__ __align__(16) __half g_C[(size_t)NN * 128];
__device__ __align__(16) float g_pool[GG * 32];
__device__ int g_is64;

struct __align__(8) h4 { __half2 a, b; };   // 4 halves, one 8B access

__device__ __forceinline__ float4 h4_to_f4(h4 v) {
    float2 f0 = __half22float2(v.a);
    float2 f1 = __half22float2(v.b);
    return make_float4(f0.x, f0.y, f1.x, f1.y);
}
__device__ __forceinline__ h4 f4_to_h4(float4 v) {
    h4 r;
    r.a = __floats2half2_rn(v.x, v.y);
    r.b = __floats2half2_rn(v.z, v.w);
    return r;
}

// ---------------- init + dtype detect ----------------
// int64 node ids < 2^31 => every odd 32-bit word is 0. int32 => random ids.
__global__ void k_init_detect(const int* __restrict__ raw, int n) {
    int i = blockIdx.x * blockDim.x + threadIdx.x;
    if (i < n) {
        g_deg[i] = 1.0f;   // self loop weight
        g_cnt[i] = 0;
        g_cur[i] = 0;
    }
    if (blockIdx.x == 0) {
        __shared__ int any;
        if (threadIdx.x == 0) any = 0;
        __syncthreads();
        int v = 0;
        for (int k = threadIdx.x; k < 2048; k += blockDim.x) v |= raw[2 * k + 1];
        if (v) atomicOr(&any, 1);
        __syncthreads();
        if (threadIdx.x == 0) g_is64 = (any == 0) ? 1 : 0;
    }
}

__global__ void k_edges_pre(const void* __restrict__ ei,
                            const float* __restrict__ w, int e) {
    int i = blockIdx.x * blockDim.x + threadIdx.x;
    if (i >= e) return;
    int s, d;
    if (g_is64) {
        const long long* p = (const long long*)ei;
        s = (int)p[i];
        d = (int)p[(size_t)e + i];
    } else {
        const int* p = (const int*)ei;
        s = p[i];
        d = p[e + i];
    }
    g_src[i] = s;
    g_dst[i] = d;
    atomicAdd(&g_deg[d], w[i]);
    atomicAdd(&g_cnt[d], 1);
}

// ---------------- scan of g_cnt -> g_off ----------------

__global__ void k_scan1(int n) {   // 1024 threads/block, chunk=1024
    __shared__ int s[1024];
    int t = threadIdx.x;
    int base = blockIdx.x * 1024;
    int v = (base + t < n) ? g_cnt[base + t] : 0;
    s[t] = v;
    __syncthreads();
    for (int d = 1; d < 1024; d <<= 1) {
        int x = (t >= d) ? s[t - d] : 0;
        __syncthreads();
        s[t] += x;
        __syncthreads();
    }
    if (base + t < n) g_off[base + t + 1] = s[t];
    if (t == 1023) g_aux[blockIdx.x] = s[1023];
}

__global__ void k_scan2(int naux) {  // single block
    __shared__ int s[1024];
    int t = threadIdx.x;
    s[t] = (t < naux) ? g_aux[t] : 0;
    __syncthreads();
    for (int d = 1; d < 1024; d <<= 1) {
        int x = (t >= d) ? s[t - d] : 0;
        __syncthreads();
        s[t] += x;
        __syncthreads();
    }
    if (t < naux) g_aux[t] = (t > 0) ? s[t - 1] : 0;
}

// scan fixup + dis + pool zero
__global__ void k_scan3_dis(int n) {
    int i = blockIdx.x * blockDim.x + threadIdx.x;
    if (i < GG * 32) g_pool[i] = 0.f;
    if (i >= n) return;
    g_off[i + 1] += g_aux[i >> 10];
    if (i == 0) g_off[0] = 0;
    float dg = g_deg[i];
    g_deg[i] = (dg > 0.f) ? rsqrtf(dg) : 0.f;
}

// norm + CSR fill
__global__ void k_norm_fill(const float* __restrict__ w, int e) {
    int i = blockIdx.x * blockDim.x + threadIdx.x;
    if (i >= e) return;
    int s = g_src[i];
    int d = g_dst[i];
    float nm = g_deg[s] * w[i] * g_deg[d];
    int pos = g_off[d] + atomicAdd(&g_cur[d], 1);
    g_cpack[pos] = make_int2(s, __float_as_int(nm));
}

// ---------------- layer 1: gather x -> ax (fp32) ----------------

__global__ void k_gather_ax(const float* __restrict__ x, int n) {
    int i = blockIdx.x * blockDim.x + threadIdx.x;
    if (i >= n) return;
    float d = g_deg[i];
    float acc = d * d * x[i];
    int r0 = g_off[i], r1 = g_off[i + 1];
    for (int j = r0; j < r1; j++) {
        int2 p = g_cpack[j];
        acc = fmaf(__int_as_float(p.y), x[p.x], acc);
    }
    g_ax[i] = acc;
}

// ---------------- wmma GEMM core (shared epilogue) ----------------
// Block: 128 threads = 4 warps; 64 rows x FO per block.
// As: [64][AP] fp16 staged (bias+relu applied). Wsh: [FI][FO] fp16.

template <int FI, int FO>
__device__ __forceinline__ void gemm_mma_core(
    const __half* As, int AP, const __half* Wsh, float* Cs,
    __half* __restrict__ tbuf, int n0, int n, int wid, int lane) {
    wmma::fragment<wmma::accumulator, 16, 16, 16, float> cfrag[FO / 16];
#pragma unroll
    for (int t = 0; t < FO / 16; t++) wmma::fill_fragment(cfrag[t], 0.f);

#pragma unroll
    for (int ks = 0; ks < FI / 16; ks++) {
        wmma::fragment<wmma::matrix_a, 16, 16, 16, __half, wmma::row_major> afrag;
        wmma::load_matrix_sync(afrag, As + (wid * 16) * AP + ks * 16, AP);
#pragma unroll
        for (int t = 0; t < FO / 16; t++) {
            wmma::fragment<wmma::matrix_b, 16, 16, 16, __half, wmma::row_major> bfrag;
            wmma::load_matrix_sync(bfrag, Wsh + (ks * 16) * FO + t * 16, FO);
            wmma::mma_sync(cfrag[t], afrag, bfrag, cfrag[t]);
        }
    }

    float* myCs = Cs + wid * 256;
    const int r = lane >> 1;
    const int c0 = (lane & 1) * 8;
    const int gn = n0 + wid * 16 + r;
#pragma unroll
    for (int t = 0; t < FO / 16; t++) {
        wmma::store_matrix_sync(myCs, cfrag[t], 16, wmma::mem_row_major);
        __syncwarp();
        if (gn < n) {
            float4 v0 = *reinterpret_cast<const float4*>(myCs + r * 16 + c0);
            float4 v1 = *reinterpret_cast<const float4*>(myCs + r * 16 + c0 + 4);
            h4* dst = reinterpret_cast<h4*>(tbuf + (size_t)gn * FO + t * 16 + c0);
            dst[0] = f4_to_h4(v0);
            dst[1] = f4_to_h4(v1);
        }
        __syncwarp();
    }
}

// ---------------- layer 2 GEMM (fused layer-1 expand): FI=128, FO=96 --------
// h1[node][k] = relu(ax[node]*W1[k] + b1[k]) staged to smem fp16.

__global__ __launch_bounds__(128)
void k_gemm2_mma(const float* __restrict__ W1, const float* __restrict__ b1,
                 const float* __restrict__ W2,
                 __half* __restrict__ tbuf, int n) {
    constexpr int FI = 128, FO = 96, AP = FI + 8;
    __shared__ __align__(32) __half As[64 * AP];          // 17408 B
    __shared__ __align__(32) __half Wsh[FI * FO];         // 24576 B
    __shared__ __align__(32) float Cs[4 * 256];           // 4096 B
    __shared__ __align__(16) float W1s[FI], b1s[FI], axs[64];
    const int tid = threadIdx.x;
    const int wid = tid >> 5, lane = tid & 31;
    const int n0 = blockIdx.x * 64;

    W1s[tid] = W1[tid];
    b1s[tid] = b1[tid];
    if (tid < 64) {
        int nd = n0 + tid;
        axs[tid] = (nd < n) ? g_ax[nd] : 0.f;
    }
    for (int i = tid; i < FI * FO; i += 128) Wsh[i] = __float2half_rn(W2[i]);
    __syncthreads();

    // stage h1: thread owns node = tid&63, k = (tid>>6) + 2m
    {
        int node = tid & 63;
        float ax = axs[node];
        __half* row = As + node * AP;
#pragma unroll 8
        for (int m = 0; m < 64; m++) {
            int k = (tid >> 6) + 2 * m;
            row[k] = __float2half_rn(fmaxf(fmaf(ax, W1s[k], b1s[k]), 0.f));
        }
    }
    __syncthreads();

    gemm_mma_core<FI, FO>(As, AP, Wsh, Cs, tbuf, n0, n, wid, lane);
}

// ---------------- generic GEMM layers 3,4: relu(in+bias) @ W ----------------

template <int FI, int FO>
__global__ __launch_bounds__(128)
void k_gemm_mma(const __half* __restrict__ hin, const float* __restrict__ bin,
                const float* __restrict__ W,
                __half* __restrict__ tbuf, int n) {
    constexpr int AP = FI + 8;
    constexpr int FI4 = FI / 4;
    __shared__ __align__(32) __half As[64 * AP];
    __shared__ __align__(32) __half Wsh[FI * FO];
    __shared__ __align__(32) float Cs[4 * 256];
    __shared__ __align__(16) float bs[FI];
    const int tid = threadIdx.x;
    const int wid = tid >> 5, lane = tid & 31;
    const int n0 = blockIdx.x * 64;

    for (int i = tid; i < FI; i += 128) bs[i] = bin[i];
    for (int i = tid; i < FI * FO; i += 128) Wsh[i] = __float2half_rn(W[i]);
    __syncthreads();

    for (int i = tid; i < 64 * FI4; i += 128) {
        int node = i / FI4, c = i % FI4;
        int gn = n0 + node;
        float4 v = make_float4(0.f, 0.f, 0.f, 0.f);
        if (gn < n) {
            float4 r = h4_to_f4(*reinterpret_cast<const h4*>(hin + (size_t)gn * FI + c * 4));
            v.x = fmaxf(r.x + bs[c * 4 + 0], 0.f);
            v.y = fmaxf(r.y + bs[c * 4 + 1], 0.f);
            v.z = fmaxf(r.z + bs[c * 4 + 2], 0.f);
            v.w = fmaxf(r.w + bs[c * 4 + 3], 0.f);
        }
        *reinterpret_cast<h4*>(As + node * AP + c * 4) = f4_to_h4(v);
    }
    __syncthreads();

    gemm_mma_core<FI, FO>(As, AP, Wsh, Cs, tbuf, n0, n, wid, lane);
}

// ---------------- per-dst gather: out[dst] = d2*t[dst] + sum nm*t[src] ------
// Thread = (dst, 4-feature chunk). fp16 loads/stores, fp32 accumulate.

template <int FO>
__global__ __launch_bounds__(256)
void k_gather(const __half* __restrict__ t, __half* __restrict__ out, int n) {
    constexpr int FO4 = FO / 4;
    int idx = blockIdx.x * 256 + threadIdx.x;
    if (idx >= n * FO4) return;
    int dst = idx / FO4;
    int c = idx - dst * FO4;
    const int r0 = g_off[dst], r1 = g_off[dst + 1];
    float d = g_deg[dst];
    float d2 = d * d;
    const size_t co = (size_t)c * 4;
    float4 a = h4_to_f4(*reinterpret_cast<const h4*>(t + (size_t)dst * FO + co));
    a.x *= d2; a.y *= d2; a.z *= d2; a.w *= d2;
    int j = r0;
    for (; j + 1 < r1; j += 2) {
        int2 p0 = g_cpack[j], p1 = g_cpack[j + 1];
        float m0 = __int_as_float(p0.y), m1 = __int_as_float(p1.y);
        float4 v0 = h4_to_f4(*reinterpret_cast<const h4*>(t + (size_t)p0.x * FO + co));
        float4 v1 = h4_to_f4(*reinterpret_cast<const h4*>(t + (size_t)p1.x * FO + co));
        a.x = fmaf(m0, v0.x, a.x); a.y = fmaf(m0, v0.y, a.y);
        a.z = fmaf(m0, v0.z, a.z); a.w = fmaf(m0, v0.w, a.w);
        a.x = fmaf(m1, v1.x, a.x); a.y = fmaf(m1, v1.y, a.y);
        a.z = fmaf(m1, v1.z, a.z); a.w = fmaf(m1, v1.w, a.w);
    }
    if (j < r1) {
        int2 p0 = g_cpack[j];
        float m0 = __int_as_float(p0.y);
        float4 v0 = h4_to_f4(*reinterpret_cast<const h4*>(t + (size_t)p0.x * FO + co));
        a.x = fmaf(m0, v0.x, a.x); a.y = fmaf(m0, v0.y, a.y);
        a.z = fmaf(m0, v0.z, a.z); a.w = fmaf(m0, v0.w, a.w);
    }
    *reinterpret_cast<h4*>(out + (size_t)dst * FO + co) = f4_to_h4(a);
}

// ---------------- pooling ----------------

// block (32,8), each block covers 2048 nodes; batch sorted -> running max
__global__ void k_pool(const __half* __restrict__ h, const float* __restrict__ b4,
                       const void* __restrict__ batch, int n) {
    const int tx = threadIdx.x;   // feature lane
    const int ty = threadIdx.y;   // node row
    const int base = blockIdx.x * 2048;
    const float bb = __ldg(&b4[tx]);
    const int is64 = g_is64;
    const long long* b64 = (const long long*)batch;
    const int* b32 = (const int*)batch;
    float rmax = 0.f;
    int curg = -1;
    for (int off = ty; off < 2048; off += 8) {
        int nd = base + off;
        if (nd >= n) break;
        int g = is64 ? (int)b64[nd] : b32[nd];
        float v = fmaxf(__half2float(h[(size_t)nd * 32 + tx]) + bb, 0.f);
        if (g != curg) {
            if (curg >= 0)
                atomicMax(reinterpret_cast<int*>(&g_pool[curg * 32 + tx]),
                          __float_as_int(rmax));
            curg = g;
            rmax = v;
        } else {
            rmax = fmaxf(rmax, v);
        }
    }
    if (curg >= 0)
        atomicMax(reinterpret_cast<int*>(&g_pool[curg * 32 + tx]),
                  __float_as_int(rmax));
}

// ---------------- final MLP: relu(g@W5+b5)@W6+b6 ----------------

__global__ void k_mlp(const float* __restrict__ W5, const float* __restrict__ b5,
                      const float* __restrict__ W6, const float* __restrict__ b6,
                      float* __restrict__ out) {
    __shared__ float W5s[32 * 32], b5s[32], W6s[64], b6s[2];
    int t = threadIdx.x;   // 64 threads = 64 graphs
    for (int i = t; i < 1024; i += 64) W5s[i] = W5[i];
    if (t < 32) b5s[t] = b5[t];
    W6s[t] = W6[t];
    if (t < 2) b6s[t] = b6[t];
    __syncthreads();
    float p[32];
#pragma unroll
    for (int k = 0; k < 32; k++) p[k] = g_pool[t * 32 + k];
    float o0 = b6s[0], o1 = b6s[1];
#pragma unroll 4
    for (int j = 0; j < 32; j++) {
        float s = b5s[j];
#pragma unroll
        for (int k = 0; k < 32; k++) s = fmaf(p[k], W5s[k * 32 + j], s);
        s = fmaxf(s, 0.f);
        o0 = fmaf(s, W6s[j * 2], o0);
        o1 = fmaf(s, W6s[j * 2 + 1], o1);
    }
    out[t * 2] = o0;
    out[t * 2 + 1] = o1;
}

// ---------------- launch ----------------

extern "C" void kernel_launch(void* const* d_in, const int* in_sizes, int n_in,
                              void* d_out, int out_size) {
    const float* x  = (const float*)d_in[0];
    const void*  ei = d_in[1];
    const float* ew = (const float*)d_in[2];
    const void*  bt = d_in[3];
    const float* W1 = (const float*)d_in[4];
    const float* b1 = (const float*)d_in[5];
    const float* W2 = (const float*)d_in[6];
    const float* b2 = (const float*)d_in[7];
    const float* W3 = (const float*)d_in[8];
    const float* b3 = (const float*)d_in[9];
    const float* W4 = (const float*)d_in[10];
    const float* b4 = (const float*)d_in[11];
    const float* W5 = (const float*)d_in[12];
    const float* b5 = (const float*)d_in[13];
    const float* W6 = (const float*)d_in[14];
    const float* b6 = (const float*)d_in[15];
    float* out = (float*)d_out;

    const int n = in_sizes[0];
    const int e = in_sizes[2];

    const int nb  = (n + 255) / 256;
    const int ebk = (e + 255) / 256;
    const int nchunks = (n + 1023) / 1024;

    k_init_detect<<<nb, 256>>>((const int*)ei, n);
    k_edges_pre<<<ebk, 256>>>(ei, ew, e);
    k_scan1<<<nchunks, 1024>>>(n);
    k_scan2<<<1, 1024>>>(nchunks);
    k_scan3_dis<<<nb, 256>>>(n);
    k_norm_fill<<<ebk, 256>>>(ew, e);
    k_gather_ax<<<nb, 256>>>(x, n);

    const int gx = (n + 63) / 64;

    __half* A; __half* B; __half* C;
    cudaGetSymbolAddress((void**)&A, g_A);
    cudaGetSymbolAddress((void**)&B, g_B);
    cudaGetSymbolAddress((void**)&C, g_C);

    // layer 2 (fused layer-1 expand): t2->B, gather -> C
    k_gemm2_mma<<<gx, 128>>>(W1, b1, W2, B, n);
    k_gather<96><<<(n * 24 + 255) / 256, 256>>>(B, C, n);

    // layer 3: in C (+b2,relu) -> t3->A, gather -> B
    k_gemm_mma<96, 64><<<gx, 128>>>(C, b2, W3, A, n);
    k_gather<64><<<(n * 16 + 255) / 256, 256>>>(A, B, n);

    // layer 4: in B (+b3,relu) -> t4->C, gather -> A
    k_gemm_mma<64, 32><<<gx, 128>>>(B, b3, W4, C, n);
    k_gather<32><<<(n * 8 + 255) / 256, 256>>>(C, A, n);

    // pool + MLP
    k_pool<<<(n + 2047) / 2048, dim3(32, 8)>>>(A, b4, bt, n);
    k_mlp<<<1, 64>>>(W5, b5, W6, b6, out);
}

// round 14
// speedup vs baseline: 1.5219x; 1.2918x over previous
#include <cuda_runtime.h>
#include <cuda_fp16.h>
#include <mma.h>
#include <cstdint>

using namespace nvcuda;

// ---------------------------------------------------------------------------
// GCN: 4 conv layers + global max pool + MLP.
// R14 = resubmit of R13 (container infra failure; source audited, unchanged).
// R13 = R12 (403.5us: fp16 h-buffers, wmma GEMMs, CSR gathers) +
//   (1) rank trick: edges_pre keeps its cnt-atomic return value -> norm_fill
//       becomes atomic-free (g_cur deleted)
//   (2) pool fused into layer-4 gather (k_pool + A-write/read deleted)
// ---------------------------------------------------------------------------

constexpr int NN = 100000;
constexpr int EE = 1600000;
constexpr int GG = 64;

__device__ __align__(16) float g_deg[NN];            // deg, then dis (in place)
__device__ __align__(16) int   g_src[EE];
__device__ __align__(16) int   g_dst[EE];
__device__ __align__(16) int   g_rank[EE];           // per-edge slot within dst
__device__ __align__(16) int2  g_cpack[EE];          // CSR by dst: (src, norm bits)
__device__ __align__(16) int   g_off[NN + 1];
__device__ __align__(16) int   g_cnt[NN];
__device__ __align__(16) int   g_aux[128];
__device__ __align__(16) float g_ax[NN];
__device__ __align__(16) __half g_A[(size_t)NN * 128];
__device__ __align__(16) __half g_B[(size_t)NN * 128];
__device__ __align__(16) __half g_C[(size_t)NN * 128];
__device__ __align__(16) float g_pool[GG * 32];
__device__ int g_is64;

struct __align__(8) h4 { __half2 a, b; };   // 4 halves, one 8B access

__device__ __forceinline__ float4 h4_to_f4(h4 v) {
    float2 f0 = __half22float2(v.a);
    float2 f1 = __half22float2(v.b);
    return make_float4(f0.x, f0.y, f1.x, f1.y);
}
__device__ __forceinline__ h4 f4_to_h4(float4 v) {
    h4 r;
    r.a = __floats2half2_rn(v.x, v.y);
    r.b = __floats2half2_rn(v.z, v.w);
    return r;
}

// ---------------- init + dtype detect ----------------
// int64 node ids < 2^31 => every odd 32-bit word is 0. int32 => random ids.
__global__ void k_init_detect(const int* __restrict__ raw, int n) {
    int i = blockIdx.x * blockDim.x + threadIdx.x;
    if (i < n) {
        g_deg[i] = 1.0f;   // self loop weight
        g_cnt[i] = 0;
    }
    if (blockIdx.x == 0) {
        __shared__ int any;
        if (threadIdx.x == 0) any = 0;
        __syncthreads();
        int v = 0;
        for (int k = threadIdx.x; k < 2048; k += blockDim.x) v |= raw[2 * k + 1];
        if (v) atomicOr(&any, 1);
        __syncthreads();
        if (threadIdx.x == 0) g_is64 = (any == 0) ? 1 : 0;
    }
}

__global__ void k_edges_pre(const void* __restrict__ ei,
                            const float* __restrict__ w, int e) {
    int i = blockIdx.x * blockDim.x + threadIdx.x;
    if (i >= e) return;
    int s, d;
    if (g_is64) {
        const long long* p = (const long long*)ei;
        s = (int)p[i];
        d = (int)p[(size_t)e + i];
    } else {
        const int* p = (const int*)ei;
        s = p[i];
        d = p[e + i];
    }
    g_src[i] = s;
    g_dst[i] = d;
    atomicAdd(&g_deg[d], w[i]);
    g_rank[i] = atomicAdd(&g_cnt[d], 1);   // keep the rank (R13)
}

// ---------------- scan of g_cnt -> g_off ----------------

__global__ void k_scan1(int n) {   // 1024 threads/block, chunk=1024
    __shared__ int s[1024];
    int t = threadIdx.x;
    int base = blockIdx.x * 1024;
    int v = (base + t < n) ? g_cnt[base + t] : 0;
    s[t] = v;
    __syncthreads();
    for (int d = 1; d < 1024; d <<= 1) {
        int x = (t >= d) ? s[t - d] : 0;
        __syncthreads();
        s[t] += x;
        __syncthreads();
    }
    if (base + t < n) g_off[base + t + 1] = s[t];
    if (t == 1023) g_aux[blockIdx.x] = s[1023];
}

__global__ void k_scan2(int naux) {  // single block
    __shared__ int s[1024];
    int t = threadIdx.x;
    s[t] = (t < naux) ? g_aux[t] : 0;
    __syncthreads();
    for (int d = 1; d < 1024; d <<= 1) {
        int x = (t >= d) ? s[t - d] : 0;
        __syncthreads();
        s[t] += x;
        __syncthreads();
    }
    if (t < naux) g_aux[t] = (t > 0) ? s[t - 1] : 0;
}

// scan fixup + dis + pool zero
__global__ void k_scan3_dis(int n) {
    int i = blockIdx.x * blockDim.x + threadIdx.x;
    if (i < GG * 32) g_pool[i] = 0.f;
    if (i >= n) return;
    g_off[i + 1] += g_aux[i >> 10];
    if (i == 0) g_off[0] = 0;
    float dg = g_deg[i];
    g_deg[i] = (dg > 0.f) ? rsqrtf(dg) : 0.f;
}

// norm + CSR fill (atomic-free via rank)
__global__ void k_norm_fill(const float* __restrict__ w, int e) {
    int i = blockIdx.x * blockDim.x + threadIdx.x;
    if (i >= e) return;
    int s = g_src[i];
    int d = g_dst[i];
    float nm = g_deg[s] * w[i] * g_deg[d];
    int pos = g_off[d] + g_rank[i];
    g_cpack[pos] = make_int2(s, __float_as_int(nm));
}

// ---------------- layer 1: gather x -> ax (fp32) ----------------

__global__ void k_gather_ax(const float* __restrict__ x, int n) {
    int i = blockIdx.x * blockDim.x + threadIdx.x;
    if (i >= n) return;
    float d = g_deg[i];
    float acc = d * d * x[i];
    int r0 = g_off[i], r1 = g_off[i + 1];
    for (int j = r0; j < r1; j++) {
        int2 p = g_cpack[j];
        acc = fmaf(__int_as_float(p.y), x[p.x], acc);
    }
    g_ax[i] = acc;
}

// ---------------- wmma GEMM core (shared epilogue) ----------------
// Block: 128 threads = 4 warps; 64 rows x FO per block.
// As: [64][AP] fp16 staged (bias+relu applied). Wsh: [FI][FO] fp16.

template <int FI, int FO>
__device__ __forceinline__ void gemm_mma_core(
    const __half* As, int AP, const __half* Wsh, float* Cs,
    __half* __restrict__ tbuf, int n0, int n, int wid, int lane) {
    wmma::fragment<wmma::accumulator, 16, 16, 16, float> cfrag[FO / 16];
#pragma unroll
    for (int t = 0; t < FO / 16; t++) wmma::fill_fragment(cfrag[t], 0.f);

#pragma unroll
    for (int ks = 0; ks < FI / 16; ks++) {
        wmma::fragment<wmma::matrix_a, 16, 16, 16, __half, wmma::row_major> afrag;
        wmma::load_matrix_sync(afrag, As + (wid * 16) * AP + ks * 16, AP);
#pragma unroll
        for (int t = 0; t < FO / 16; t++) {
            wmma::fragment<wmma::matrix_b, 16, 16, 16, __half, wmma::row_major> bfrag;
            wmma::load_matrix_sync(bfrag, Wsh + (ks * 16) * FO + t * 16, FO);
            wmma::mma_sync(cfrag[t], afrag, bfrag, cfrag[t]);
        }
    }

    float* myCs = Cs + wid * 256;
    const int r = lane >> 1;
    const int c0 = (lane & 1) * 8;
    const int gn = n0 + wid * 16 + r;
#pragma unroll
    for (int t = 0; t < FO / 16; t++) {
        wmma::store_matrix_sync(myCs, cfrag[t], 16, wmma::mem_row_major);
        __syncwarp();
        if (gn < n) {
            float4 v0 = *reinterpret_cast<const float4*>(myCs + r * 16 + c0);
            float4 v1 = *reinterpret_cast<const float4*>(myCs + r * 16 + c0 + 4);
            h4* dst = reinterpret_cast<h4*>(tbuf + (size_t)gn * FO + t * 16 + c0);
            dst[0] = f4_to_h4(v0);
            dst[1] = f4_to_h4(v1);
        }
        __syncwarp();
    }
}

// ---------------- layer 2 GEMM (fused layer-1 expand): FI=128, FO=96 --------
// h1[node][k] = relu(ax[node]*W1[k] + b1[k]) staged to smem fp16.

__global__ __launch_bounds__(128)
void k_gemm2_mma(const float* __restrict__ W1, const float* __restrict__ b1,
                 const float* __restrict__ W2,
                 __half* __restrict__ tbuf, int n) {
    constexpr int FI = 128, FO = 96, AP = FI + 8;
    __shared__ __align__(32) __half As[64 * AP];
    __shared__ __align__(32) __half Wsh[FI * FO];
    __shared__ __align__(32) float Cs[4 * 256];
    __shared__ __align__(16) float W1s[FI], b1s[FI], axs[64];
    const int tid = threadIdx.x;
    const int wid = tid >> 5, lane = tid & 31;
    const int n0 = blockIdx.x * 64;

    W1s[tid] = W1[tid];
    b1s[tid] = b1[tid];
    if (tid < 64) {
        int nd = n0 + tid;
        axs[tid] = (nd < n) ? g_ax[nd] : 0.f;
    }
    for (int i = tid; i < FI * FO; i += 128) Wsh[i] = __float2half_rn(W2[i]);
    __syncthreads();

    // stage h1: thread owns node = tid&63, k = (tid>>6) + 2m
    {
        int node = tid & 63;
        float ax = axs[node];
        __half* row = As + node * AP;
#pragma unroll 8
        for (int m = 0; m < 64; m++) {
            int k = (tid >> 6) + 2 * m;
            row[k] = __float2half_rn(fmaxf(fmaf(ax, W1s[k], b1s[k]), 0.f));
        }
    }
    __syncthreads();

    gemm_mma_core<FI, FO>(As, AP, Wsh, Cs, tbuf, n0, n, wid, lane);
}

// ---------------- generic GEMM layers 3,4: relu(in+bias) @ W ----------------

template <int FI, int FO>
__global__ __launch_bounds__(128)
void k_gemm_mma(const __half* __restrict__ hin, const float* __restrict__ bin,
                const float* __restrict__ W,
                __half* __restrict__ tbuf, int n) {
    constexpr int AP = FI + 8;
    constexpr int FI4 = FI / 4;
    __shared__ __align__(32) __half As[64 * AP];
    __shared__ __align__(32) __half Wsh[FI * FO];
    __shared__ __align__(32) float Cs[4 * 256];
    __shared__ __align__(16) float bs[FI];
    const int tid = threadIdx.x;
    const int wid = tid >> 5, lane = tid & 31;
    const int n0 = blockIdx.x * 64;

    for (int i = tid; i < FI; i += 128) bs[i] = bin[i];
    for (int i = tid; i < FI * FO; i += 128) Wsh[i] = __float2half_rn(W[i]);
    __syncthreads();

    for (int i = tid; i < 64 * FI4; i += 128) {
        int node = i / FI4, c = i % FI4;
        int gn = n0 + node;
        float4 v = make_float4(0.f, 0.f, 0.f, 0.f);
        if (gn < n) {
            float4 r = h4_to_f4(*reinterpret_cast<const h4*>(hin + (size_t)gn * FI + c * 4));
            v.x = fmaxf(r.x + bs[c * 4 + 0], 0.f);
            v.y = fmaxf(r.y + bs[c * 4 + 1], 0.f);
            v.z = fmaxf(r.z + bs[c * 4 + 2], 0.f);
            v.w = fmaxf(r.w + bs[c * 4 + 3], 0.f);
        }
        *reinterpret_cast<h4*>(As + node * AP + c * 4) = f4_to_h4(v);
    }
    __syncthreads();

    gemm_mma_core<FI, FO>(As, AP, Wsh, Cs, tbuf, n0, n, wid, lane);
}

// ---------------- per-dst gather: out[dst] = d2*t[dst] + sum nm*t[src] ------
// Thread = (dst, 4-feature chunk). fp16 loads/stores, fp32 accumulate.

template <int FO>
__global__ __launch_bounds__(256)
void k_gather(const __half* __restrict__ t, __half* __restrict__ out, int n) {
    constexpr int FO4 = FO / 4;
    int idx = blockIdx.x * 256 + threadIdx.x;
    if (idx >= n * FO4) return;
    int dst = idx / FO4;
    int c = idx - dst * FO4;
    const int r0 = g_off[dst], r1 = g_off[dst + 1];
    float d = g_deg[dst];
    float d2 = d * d;
    const size_t co = (size_t)c * 4;
    float4 a = h4_to_f4(*reinterpret_cast<const h4*>(t + (size_t)dst * FO + co));
    a.x *= d2; a.y *= d2; a.z *= d2; a.w *= d2;
    int j = r0;
    for (; j + 1 < r1; j += 2) {
        int2 p0 = g_cpack[j], p1 = g_cpack[j + 1];
        float m0 = __int_as_float(p0.y), m1 = __int_as_float(p1.y);
        float4 v0 = h4_to_f4(*reinterpret_cast<const h4*>(t + (size_t)p0.x * FO + co));
        float4 v1 = h4_to_f4(*reinterpret_cast<const h4*>(t + (size_t)p1.x * FO + co));
        a.x = fmaf(m0, v0.x, a.x); a.y = fmaf(m0, v0.y, a.y);
        a.z = fmaf(m0, v0.z, a.z); a.w = fmaf(m0, v0.w, a.w);
        a.x = fmaf(m1, v1.x, a.x); a.y = fmaf(m1, v1.y, a.y);
        a.z = fmaf(m1, v1.z, a.z); a.w = fmaf(m1, v1.w, a.w);
    }
    if (j < r1) {
        int2 p0 = g_cpack[j];
        float m0 = __int_as_float(p0.y);
        float4 v0 = h4_to_f4(*reinterpret_cast<const h4*>(t + (size_t)p0.x * FO + co));
        a.x = fmaf(m0, v0.x, a.x); a.y = fmaf(m0, v0.y, a.y);
        a.z = fmaf(m0, v0.z, a.z); a.w = fmaf(m0, v0.w, a.w);
    }
    *reinterpret_cast<h4*>(out + (size_t)dst * FO + co) = f4_to_h4(a);
}

// ---------------- layer-4 gather fused with pooling (FO=32) ----------------
// Thread = (dst, 4-feature chunk), 8 chunks/dst, 32 dsts/block.
// Gathers, applies bias+relu, block-reduces max per graph (<=2 graphs per
// block of 32 sorted nodes), then <=64 global atomicMax per block.

__global__ __launch_bounds__(256)
void k_gather_pool(const __half* __restrict__ t, const float* __restrict__ b4,
                   const void* __restrict__ batch, int n) {
    __shared__ int smax[2][32];
    const int tid = threadIdx.x;
    if (tid < 64) smax[tid >> 5][tid & 31] = 0;
    __syncthreads();

    const int idx = blockIdx.x * 256 + tid;
    const int dst = idx >> 3;
    const int c = idx & 7;
    const int node0 = (blockIdx.x * 256) >> 3;   // block's first node
    const int is64 = g_is64;
    const long long* b64 = (const long long*)batch;
    const int* b32 = (const int*)batch;
    const int gmin = (node0 < n) ? (is64 ? (int)b64[node0] : b32[node0]) : 0;

    if (dst < n) {
        const int r0 = g_off[dst], r1 = g_off[dst + 1];
        float d = g_deg[dst];
        float d2 = d * d;
        const size_t co = (size_t)c * 4;
        float4 a = h4_to_f4(*reinterpret_cast<const h4*>(t + (size_t)dst * 32 + co));
        a.x *= d2; a.y *= d2; a.z *= d2; a.w *= d2;
        int j = r0;
        for (; j + 1 < r1; j += 2) {
            int2 p0 = g_cpack[j], p1 = g_cpack[j + 1];
            float m0 = __int_as_float(p0.y), m1 = __int_as_float(p1.y);
            float4 v0 = h4_to_f4(*reinterpret_cast<const h4*>(t + (size_t)p0.x * 32 + co));
            float4 v1 = h4_to_f4(*reinterpret_cast<const h4*>(t + (size_t)p1.x * 32 + co));
            a.x = fmaf(m0, v0.x, a.x); a.y = fmaf(m0, v0.y, a.y);
            a.z = fmaf(m0, v0.z, a.z); a.w = fmaf(m0, v0.w, a.w);
            a.x = fmaf(m1, v1.x, a.x); a.y = fmaf(m1, v1.y, a.y);
            a.z = fmaf(m1, v1.z, a.z); a.w = fmaf(m1, v1.w, a.w);
        }
        if (j < r1) {
            int2 p0 = g_cpack[j];
            float m0 = __int_as_float(p0.y);
            float4 v0 = h4_to_f4(*reinterpret_cast<const h4*>(t + (size_t)p0.x * 32 + co));
            a.x = fmaf(m0, v0.x, a.x); a.y = fmaf(m0, v0.y, a.y);
            a.z = fmaf(m0, v0.z, a.z); a.w = fmaf(m0, v0.w, a.w);
        }
        // bias + relu
        const int f0 = c * 4;
        float r0f = fmaxf(a.x + __ldg(&b4[f0 + 0]), 0.f);
        float r1f = fmaxf(a.y + __ldg(&b4[f0 + 1]), 0.f);
        float r2f = fmaxf(a.z + __ldg(&b4[f0 + 2]), 0.f);
        float r3f = fmaxf(a.w + __ldg(&b4[f0 + 3]), 0.f);
        // graph-local reduction (values >= 0 -> int compare valid)
        int g = is64 ? (int)b64[dst] : b32[dst];
        int l = g - gmin;
        if (l <= 1) {
            atomicMax(&smax[l][f0 + 0], __float_as_int(r0f));
            atomicMax(&smax[l][f0 + 1], __float_as_int(r1f));
            atomicMax(&smax[l][f0 + 2], __float_as_int(r2f));
            atomicMax(&smax[l][f0 + 3], __float_as_int(r3f));
        } else {  // safety net (cannot happen with graph size >> 32)
            atomicMax(reinterpret_cast<int*>(&g_pool[g * 32 + f0 + 0]), __float_as_int(r0f));
            atomicMax(reinterpret_cast<int*>(&g_pool[g * 32 + f0 + 1]), __float_as_int(r1f));
            atomicMax(reinterpret_cast<int*>(&g_pool[g * 32 + f0 + 2]), __float_as_int(r2f));
            atomicMax(reinterpret_cast<int*>(&g_pool[g * 32 + f0 + 3]), __float_as_int(r3f));
        }
    }
    __syncthreads();
    if (tid < 64) {
        int l = tid >> 5, f = tid & 31;
        int v = smax[l][f];
        int gg = gmin + l;
        if (v != 0 && gg < GG)
            atomicMax(reinterpret_cast<int*>(&g_pool[gg * 32 + f]), v);
    }
}

// ---------------- final MLP: relu(g@W5+b5)@W6+b6 ----------------

__global__ void k_mlp(const float* __restrict__ W5, const float* __restrict__ b5,
                      const float* __restrict__ W6, const float* __restrict__ b6,
                      float* __restrict__ out) {
    __shared__ float W5s[32 * 32], b5s[32], W6s[64], b6s[2];
    int t = threadIdx.x;   // 64 threads = 64 graphs
    for (int i = t; i < 1024; i += 64) W5s[i] = W5[i];
    if (t < 32) b5s[t] = b5[t];
    W6s[t] = W6[t];
    if (t < 2) b6s[t] = b6[t];
    __syncthreads();
    float p[32];
#pragma unroll
    for (int k = 0; k < 32; k++) p[k] = g_pool[t * 32 + k];
    float o0 = b6s[0], o1 = b6s[1];
#pragma unroll 4
    for (int j = 0; j < 32; j++) {
        float s = b5s[j];
#pragma unroll
        for (int k = 0; k < 32; k++) s = fmaf(p[k], W5s[k * 32 + j], s);
        s = fmaxf(s, 0.f);
        o0 = fmaf(s, W6s[j * 2], o0);
        o1 = fmaf(s, W6s[j * 2 + 1], o1);
    }
    out[t * 2] = o0;
    out[t * 2 + 1] = o1;
}

// ---------------- launch ----------------

extern "C" void kernel_launch(void* const* d_in, const int* in_sizes, int n_in,
                              void* d_out, int out_size) {
    const float* x  = (const float*)d_in[0];
    const void*  ei = d_in[1];
    const float* ew = (const float*)d_in[2];
    const void*  bt = d_in[3];
    const float* W1 = (const float*)d_in[4];
    const float* b1 = (const float*)d_in[5];
    const float* W2 = (const float*)d_in[6];
    const float* b2 = (const float*)d_in[7];
    const float* W3 = (const float*)d_in[8];
    const float* b3 = (const float*)d_in[9];
    const float* W4 = (const float*)d_in[10];
    const float* b4 = (const float*)d_in[11];
    const float* W5 = (const float*)d_in[12];
    const float* b5 = (const float*)d_in[13];
    const float* W6 = (const float*)d_in[14];
    const float* b6 = (const float*)d_in[15];
    float* out = (float*)d_out;

    const int n = in_sizes[0];
    const int e = in_sizes[2];

    const int nb  = (n + 255) / 256;
    const int ebk = (e + 255) / 256;
    const int nchunks = (n + 1023) / 1024;

    k_init_detect<<<nb, 256>>>((const int*)ei, n);
    k_edges_pre<<<ebk, 256>>>(ei, ew, e);
    k_scan1<<<nchunks, 1024>>>(n);
    k_scan2<<<1, 1024>>>(nchunks);
    k_scan3_dis<<<nb, 256>>>(n);
    k_norm_fill<<<ebk, 256>>>(ew, e);
    k_gather_ax<<<nb, 256>>>(x, n);

    const int gx = (n + 63) / 64;

    __half* A; __half* B; __half* C;
    cudaGetSymbolAddress((void**)&A, g_A);
    cudaGetSymbolAddress((void**)&B, g_B);
    cudaGetSymbolAddress((void**)&C, g_C);

    // layer 2 (fused layer-1 expand): t2->B, gather -> C
    k_gemm2_mma<<<gx, 128>>>(W1, b1, W2, B, n);
    k_gather<96><<<(n * 24 + 255) / 256, 256>>>(B, C, n);

    // layer 3: in C (+b2,relu) -> t3->A, gather -> B
    k_gemm_mma<96, 64><<<gx, 128>>>(C, b2, W3, A, n);
    k_gather<64><<<(n * 16 + 255) / 256, 256>>>(A, B, n);

    // layer 4: in B (+b3,relu) -> t4->C, gather fused with pool -> g_pool
    k_gemm_mma<64, 32><<<gx, 128>>>(B, b3, W4, C, n);
    k_gather_pool<<<(n * 8 + 255) / 256, 256>>>(C, b4, bt, n);

    // MLP
    k_mlp<<<1, 64>>>(W5, b5, W6, b6, out);
}

// round 15
// speedup vs baseline: 1.5372x; 1.0100x over previous
#include <cuda_runtime.h>
#include <cuda_fp16.h>
#include <mma.h>
#include <cstdint>

using namespace nvcuda;

// ---------------------------------------------------------------------------
// GCN: 4 conv layers + global max pool + MLP.
// R15 = R14 (312.3us) +
//   (1) layer-1 Ax fused into norm_fill via red.global.add (k_gather_ax
//       deleted; safe now that norm_fill has no other atomic)
//   (2) 4-wide edge unroll in gathers (MLP 2 -> 4)
// ---------------------------------------------------------------------------

constexpr int NN = 100000;
constexpr int EE = 1600000;
constexpr int GG = 64;

__device__ __align__(16) float g_deg[NN];            // deg, then dis (in place)
__device__ __align__(16) int   g_src[EE];
__device__ __align__(16) int   g_dst[EE];
__device__ __align__(16) int   g_rank[EE];           // per-edge slot within dst
__device__ __align__(16) int2  g_cpack[EE];          // CSR by dst: (src, norm bits)
__device__ __align__(16) int   g_off[NN + 1];
__device__ __align__(16) int   g_cnt[NN];
__device__ __align__(16) int   g_aux[128];
__device__ __align__(16) float g_ax[NN];
__device__ __align__(16) __half g_A[(size_t)NN * 128];
__device__ __align__(16) __half g_B[(size_t)NN * 128];
__device__ __align__(16) __half g_C[(size_t)NN * 128];
__device__ __align__(16) float g_pool[GG * 32];
__device__ int g_is64;

struct __align__(8) h4 { __half2 a, b; };   // 4 halves, one 8B access

__device__ __forceinline__ float4 h4_to_f4(h4 v) {
    float2 f0 = __half22float2(v.a);
    float2 f1 = __half22float2(v.b);
    return make_float4(f0.x, f0.y, f1.x, f1.y);
}
__device__ __forceinline__ h4 f4_to_h4(float4 v) {
    h4 r;
    r.a = __floats2half2_rn(v.x, v.y);
    r.b = __floats2half2_rn(v.z, v.w);
    return r;
}
__device__ __forceinline__ void red_add_f32(float* p, float v) {
    asm volatile("red.global.add.f32 [%0], %1;" :: "l"(p), "f"(v) : "memory");
}
__device__ __forceinline__ void fma4(float4& a, float m, float4 v) {
    a.x = fmaf(m, v.x, a.x); a.y = fmaf(m, v.y, a.y);
    a.z = fmaf(m, v.z, a.z); a.w = fmaf(m, v.w, a.w);
}

// ---------------- init + dtype detect ----------------
// int64 node ids < 2^31 => every odd 32-bit word is 0. int32 => random ids.
__global__ void k_init_detect(const int* __restrict__ raw, int n) {
    int i = blockIdx.x * blockDim.x + threadIdx.x;
    if (i < n) {
        g_deg[i] = 1.0f;   // self loop weight
        g_cnt[i] = 0;
    }
    if (blockIdx.x == 0) {
        __shared__ int any;
        if (threadIdx.x == 0) any = 0;
        __syncthreads();
        int v = 0;
        for (int k = threadIdx.x; k < 2048; k += blockDim.x) v |= raw[2 * k + 1];
        if (v) atomicOr(&any, 1);
        __syncthreads();
        if (threadIdx.x == 0) g_is64 = (any == 0) ? 1 : 0;
    }
}

__global__ void k_edges_pre(const void* __restrict__ ei,
                            const float* __restrict__ w, int e) {
    int i = blockIdx.x * blockDim.x + threadIdx.x;
    if (i >= e) return;
    int s, d;
    if (g_is64) {
        const long long* p = (const long long*)ei;
        s = (int)p[i];
        d = (int)p[(size_t)e + i];
    } else {
        const int* p = (const int*)ei;
        s = p[i];
        d = p[e + i];
    }
    g_src[i] = s;
    g_dst[i] = d;
    atomicAdd(&g_deg[d], w[i]);
    g_rank[i] = atomicAdd(&g_cnt[d], 1);   // keep the rank
}

// ---------------- scan of g_cnt -> g_off ----------------

__global__ void k_scan1(int n) {   // 1024 threads/block, chunk=1024
    __shared__ int s[1024];
    int t = threadIdx.x;
    int base = blockIdx.x * 1024;
    int v = (base + t < n) ? g_cnt[base + t] : 0;
    s[t] = v;
    __syncthreads();
    for (int d = 1; d < 1024; d <<= 1) {
        int x = (t >= d) ? s[t - d] : 0;
        __syncthreads();
        s[t] += x;
        __syncthreads();
    }
    if (base + t < n) g_off[base + t + 1] = s[t];
    if (t == 1023) g_aux[blockIdx.x] = s[1023];
}

__global__ void k_scan2(int naux) {  // single block
    __shared__ int s[1024];
    int t = threadIdx.x;
    s[t] = (t < naux) ? g_aux[t] : 0;
    __syncthreads();
    for (int d = 1; d < 1024; d <<= 1) {
        int x = (t >= d) ? s[t - d] : 0;
        __syncthreads();
        s[t] += x;
        __syncthreads();
    }
    if (t < naux) g_aux[t] = (t > 0) ? s[t - 1] : 0;
}

// scan fixup + dis + ax self-term + pool zero
__global__ void k_scan3_dis(const float* __restrict__ x, int n) {
    int i = blockIdx.x * blockDim.x + threadIdx.x;
    if (i < GG * 32) g_pool[i] = 0.f;
    if (i >= n) return;
    g_off[i + 1] += g_aux[i >> 10];
    if (i == 0) g_off[0] = 0;
    float dg = g_deg[i];
    float dis = (dg > 0.f) ? rsqrtf(dg) : 0.f;
    g_deg[i] = dis;
    g_ax[i] = dis * dis * x[i];   // self-loop term; edges added in norm_fill
}

// norm + CSR fill (atomic-free slot via rank) + fused layer-1 Ax (red.add)
__global__ void k_norm_fill(const float* __restrict__ w,
                            const float* __restrict__ x, int e) {
    int i = blockIdx.x * blockDim.x + threadIdx.x;
    if (i >= e) return;
    int s = g_src[i];
    int d = g_dst[i];
    float nm = g_deg[s] * w[i] * g_deg[d];
    int pos = g_off[d] + g_rank[i];
    g_cpack[pos] = make_int2(s, __float_as_int(nm));
    red_add_f32(&g_ax[d], nm * x[s]);
}

// ---------------- wmma GEMM core (shared epilogue) ----------------
// Block: 128 threads = 4 warps; 64 rows x FO per block.
// As: [64][AP] fp16 staged (bias+relu applied). Wsh: [FI][FO] fp16.

template <int FI, int FO>
__device__ __forceinline__ void gemm_mma_core(
    const __half* As, int AP, const __half* Wsh, float* Cs,
    __half* __restrict__ tbuf, int n0, int n, int wid, int lane) {
    wmma::fragment<wmma::accumulator, 16, 16, 16, float> cfrag[FO / 16];
#pragma unroll
    for (int t = 0; t < FO / 16; t++) wmma::fill_fragment(cfrag[t], 0.f);

#pragma unroll
    for (int ks = 0; ks < FI / 16; ks++) {
        wmma::fragment<wmma::matrix_a, 16, 16, 16, __half, wmma::row_major> afrag;
        wmma::load_matrix_sync(afrag, As + (wid * 16) * AP + ks * 16, AP);
#pragma unroll
        for (int t = 0; t < FO / 16; t++) {
            wmma::fragment<wmma::matrix_b, 16, 16, 16, __half, wmma::row_major> bfrag;
            wmma::load_matrix_sync(bfrag, Wsh + (ks * 16) * FO + t * 16, FO);
            wmma::mma_sync(cfrag[t], afrag, bfrag, cfrag[t]);
        }
    }

    float* myCs = Cs + wid * 256;
    const int r = lane >> 1;
    const int c0 = (lane & 1) * 8;
    const int gn = n0 + wid * 16 + r;
#pragma unroll
    for (int t = 0; t < FO / 16; t++) {
        wmma::store_matrix_sync(myCs, cfrag[t], 16, wmma::mem_row_major);
        __syncwarp();
        if (gn < n) {
            float4 v0 = *reinterpret_cast<const float4*>(myCs + r * 16 + c0);
            float4 v1 = *reinterpret_cast<const float4*>(myCs + r * 16 + c0 + 4);
            h4* dst = reinterpret_cast<h4*>(tbuf + (size_t)gn * FO + t * 16 + c0);
            dst[0] = f4_to_h4(v0);
            dst[1] = f4_to_h4(v1);
        }
        __syncwarp();
    }
}

// ---------------- layer 2 GEMM (fused layer-1 expand): FI=128, FO=96 --------
// h1[node][k] = relu(ax[node]*W1[k] + b1[k]) staged to smem fp16.

__global__ __launch_bounds__(128)
void k_gemm2_mma(const float* __restrict__ W1, const float* __restrict__ b1,
                 const float* __restrict__ W2,
                 __half* __restrict__ tbuf, int n) {
    constexpr int FI = 128, FO = 96, AP = FI + 8;
    __shared__ __align__(32) __half As[64 * AP];
    __shared__ __align__(32) __half Wsh[FI * FO];
    __shared__ __align__(32) float Cs[4 * 256];
    __shared__ __align__(16) float W1s[FI], b1s[FI], axs[64];
    const int tid = threadIdx.x;
    const int wid = tid >> 5, lane = tid & 31;
    const int n0 = blockIdx.x * 64;

    W1s[tid] = W1[tid];
    b1s[tid] = b1[tid];
    if (tid < 64) {
        int nd = n0 + tid;
        axs[tid] = (nd < n) ? g_ax[nd] : 0.f;
    }
    for (int i = tid; i < FI * FO; i += 128) Wsh[i] = __float2half_rn(W2[i]);
    __syncthreads();

    // stage h1: thread owns node = tid&63, k = (tid>>6) + 2m
    {
        int node = tid & 63;
        float ax = axs[node];
        __half* row = As + node * AP;
#pragma unroll 8
        for (int m = 0; m < 64; m++) {
            int k = (tid >> 6) + 2 * m;
            row[k] = __float2half_rn(fmaxf(fmaf(ax, W1s[k], b1s[k]), 0.f));
        }
    }
    __syncthreads();

    gemm_mma_core<FI, FO>(As, AP, Wsh, Cs, tbuf, n0, n, wid, lane);
}

// ---------------- generic GEMM layers 3,4: relu(in+bias) @ W ----------------

template <int FI, int FO>
__global__ __launch_bounds__(128)
void k_gemm_mma(const __half* __restrict__ hin, const float* __restrict__ bin,
                const float* __restrict__ W,
                __half* __restrict__ tbuf, int n) {
    constexpr int AP = FI + 8;
    constexpr int FI4 = FI / 4;
    __shared__ __align__(32) __half As[64 * AP];
    __shared__ __align__(32) __half Wsh[FI * FO];
    __shared__ __align__(32) float Cs[4 * 256];
    __shared__ __align__(16) float bs[FI];
    const int tid = threadIdx.x;
    const int wid = tid >> 5, lane = tid & 31;
    const int n0 = blockIdx.x * 64;

    for (int i = tid; i < FI; i += 128) bs[i] = bin[i];
    for (int i = tid; i < FI * FO; i += 128) Wsh[i] = __float2half_rn(W[i]);
    __syncthreads();

    for (int i = tid; i < 64 * FI4; i += 128) {
        int node = i / FI4, c = i % FI4;
        int gn = n0 + node;
        float4 v = make_float4(0.f, 0.f, 0.f, 0.f);
        if (gn < n) {
            float4 r = h4_to_f4(*reinterpret_cast<const h4*>(hin + (size_t)gn * FI + c * 4));
            v.x = fmaxf(r.x + bs[c * 4 + 0], 0.f);
            v.y = fmaxf(r.y + bs[c * 4 + 1], 0.f);
            v.z = fmaxf(r.z + bs[c * 4 + 2], 0.f);
            v.w = fmaxf(r.w + bs[c * 4 + 3], 0.f);
        }
        *reinterpret_cast<h4*>(As + node * AP + c * 4) = f4_to_h4(v);
    }
    __syncthreads();

    gemm_mma_core<FI, FO>(As, AP, Wsh, Cs, tbuf, n0, n, wid, lane);
}

// ---------------- per-dst gather: out[dst] = d2*t[dst] + sum nm*t[src] ------
// Thread = (dst, 4-feature chunk). 4-wide edge unroll (MLP=4).

template <int FO>
__global__ __launch_bounds__(256)
void k_gather(const __half* __restrict__ t, __half* __restrict__ out, int n) {
    constexpr int FO4 = FO / 4;
    int idx = blockIdx.x * 256 + threadIdx.x;
    if (idx >= n * FO4) return;
    int dst = idx / FO4;
    int c = idx - dst * FO4;
    const int r0 = g_off[dst], r1 = g_off[dst + 1];
    float d = g_deg[dst];
    float d2 = d * d;
    const size_t co = (size_t)c * 4;
    float4 a = h4_to_f4(*reinterpret_cast<const h4*>(t + (size_t)dst * FO + co));
    a.x *= d2; a.y *= d2; a.z *= d2; a.w *= d2;
    int j = r0;
    for (; j + 3 < r1; j += 4) {
        int2 p0 = g_cpack[j], p1 = g_cpack[j + 1];
        int2 p2 = g_cpack[j + 2], p3 = g_cpack[j + 3];
        float4 v0 = h4_to_f4(*reinterpret_cast<const h4*>(t + (size_t)p0.x * FO + co));
        float4 v1 = h4_to_f4(*reinterpret_cast<const h4*>(t + (size_t)p1.x * FO + co));
        float4 v2 = h4_to_f4(*reinterpret_cast<const h4*>(t + (size_t)p2.x * FO + co));
        float4 v3 = h4_to_f4(*reinterpret_cast<const h4*>(t + (size_t)p3.x * FO + co));
        fma4(a, __int_as_float(p0.y), v0);
        fma4(a, __int_as_float(p1.y), v1);
        fma4(a, __int_as_float(p2.y), v2);
        fma4(a, __int_as_float(p3.y), v3);
    }
    for (; j < r1; j++) {
        int2 p0 = g_cpack[j];
        float4 v0 = h4_to_f4(*reinterpret_cast<const h4*>(t + (size_t)p0.x * FO + co));
        fma4(a, __int_as_float(p0.y), v0);
    }
    *reinterpret_cast<h4*>(out + (size_t)dst * FO + co) = f4_to_h4(a);
}

// ---------------- layer-4 gather fused with pooling (FO=32) ----------------
// Thread = (dst, 4-feature chunk), 8 chunks/dst, 32 dsts/block.

__global__ __launch_bounds__(256)
void k_gather_pool(const __half* __restrict__ t, const float* __restrict__ b4,
                   const void* __restrict__ batch, int n) {
    __shared__ int smax[2][32];
    const int tid = threadIdx.x;
    if (tid < 64) smax[tid >> 5][tid & 31] = 0;
    __syncthreads();

    const int idx = blockIdx.x * 256 + tid;
    const int dst = idx >> 3;
    const int c = idx & 7;
    const int node0 = (blockIdx.x * 256) >> 3;   // block's first node
    const int is64 = g_is64;
    const long long* b64 = (const long long*)batch;
    const int* b32 = (const int*)batch;
    const int gmin = (node0 < n) ? (is64 ? (int)b64[node0] : b32[node0]) : 0;

    if (dst < n) {
        const int r0 = g_off[dst], r1 = g_off[dst + 1];
        float d = g_deg[dst];
        float d2 = d * d;
        const size_t co = (size_t)c * 4;
        float4 a = h4_to_f4(*reinterpret_cast<const h4*>(t + (size_t)dst * 32 + co));
        a.x *= d2; a.y *= d2; a.z *= d2; a.w *= d2;
        int j = r0;
        for (; j + 3 < r1; j += 4) {
            int2 p0 = g_cpack[j], p1 = g_cpack[j + 1];
            int2 p2 = g_cpack[j + 2], p3 = g_cpack[j + 3];
            float4 v0 = h4_to_f4(*reinterpret_cast<const h4*>(t + (size_t)p0.x * 32 + co));
            float4 v1 = h4_to_f4(*reinterpret_cast<const h4*>(t + (size_t)p1.x * 32 + co));
            float4 v2 = h4_to_f4(*reinterpret_cast<const h4*>(t + (size_t)p2.x * 32 + co));
            float4 v3 = h4_to_f4(*reinterpret_cast<const h4*>(t + (size_t)p3.x * 32 + co));
            fma4(a, __int_as_float(p0.y), v0);
            fma4(a, __int_as_float(p1.y), v1);
            fma4(a, __int_as_float(p2.y), v2);
            fma4(a, __int_as_float(p3.y), v3);
        }
        for (; j < r1; j++) {
            int2 p0 = g_cpack[j];
            float4 v0 = h4_to_f4(*reinterpret_cast<const h4*>(t + (size_t)p0.x * 32 + co));
            fma4(a, __int_as_float(p0.y), v0);
        }
        // bias + relu
        const int f0 = c * 4;
        float r0f = fmaxf(a.x + __ldg(&b4[f0 + 0]), 0.f);
        float r1f = fmaxf(a.y + __ldg(&b4[f0 + 1]), 0.f);
        float r2f = fmaxf(a.z + __ldg(&b4[f0 + 2]), 0.f);
        float r3f = fmaxf(a.w + __ldg(&b4[f0 + 3]), 0.f);
        // graph-local reduction (values >= 0 -> int compare valid)
        int g = is64 ? (int)b64[dst] : b32[dst];
        int l = g - gmin;
        if (l <= 1) {
            atomicMax(&smax[l][f0 + 0], __float_as_int(r0f));
            atomicMax(&smax[l][f0 + 1], __float_as_int(r1f));
            atomicMax(&smax[l][f0 + 2], __float_as_int(r2f));
            atomicMax(&smax[l][f0 + 3], __float_as_int(r3f));
        } else {  // safety net (cannot happen with graph size >> 32)
            atomicMax(reinterpret_cast<int*>(&g_pool[g * 32 + f0 + 0]), __float_as_int(r0f));
            atomicMax(reinterpret_cast<int*>(&g_pool[g * 32 + f0 + 1]), __float_as_int(r1f));
            atomicMax(reinterpret_cast<int*>(&g_pool[g * 32 + f0 + 2]), __float_as_int(r2f));
            atomicMax(reinterpret_cast<int*>(&g_pool[g * 32 + f0 + 3]), __float_as_int(r3f));
        }
    }
    __syncthreads();
    if (tid < 64) {
        int l = tid >> 5, f = tid & 31;
        int v = smax[l][f];
        int gg = gmin + l;
        if (v != 0 && gg < GG)
            atomicMax(reinterpret_cast<int*>(&g_pool[gg * 32 + f]), v);
    }
}

// ---------------- final MLP: relu(g@W5+b5)@W6+b6 ----------------

__global__ void k_mlp(const float* __restrict__ W5, const float* __restrict__ b5,
                      const float* __restrict__ W6, const float* __restrict__ b6,
                      float* __restrict__ out) {
    __shared__ float W5s[32 * 32], b5s[32], W6s[64], b6s[2];
    int t = threadIdx.x;   // 64 threads = 64 graphs
    for (int i = t; i < 1024; i += 64) W5s[i] = W5[i];
    if (t < 32) b5s[t] = b5[t];
    W6s[t] = W6[t];
    if (t < 2) b6s[t] = b6[t];
    __syncthreads();
    float p[32];
#pragma unroll
    for (int k = 0; k < 32; k++) p[k] = g_pool[t * 32 + k];
    float o0 = b6s[0], o1 = b6s[1];
#pragma unroll 4
    for (int j = 0; j < 32; j++) {
        float s = b5s[j];
#pragma unroll
        for (int k = 0; k < 32; k++) s = fmaf(p[k], W5s[k * 32 + j], s);
        s = fmaxf(s, 0.f);
        o0 = fmaf(s, W6s[j * 2], o0);
        o1 = fmaf(s, W6s[j * 2 + 1], o1);
    }
    out[t * 2] = o0;
    out[t * 2 + 1] = o1;
}

// ---------------- launch ----------------

extern "C" void kernel_launch(void* const* d_in, const int* in_sizes, int n_in,
                              void* d_out, int out_size) {
    const float* x  = (const float*)d_in[0];
    const void*  ei = d_in[1];
    const float* ew = (const float*)d_in[2];
    const void*  bt = d_in[3];
    const float* W1 = (const float*)d_in[4];
    const float* b1 = (const float*)d_in[5];
    const float* W2 = (const float*)d_in[6];
    const float* b2 = (const float*)d_in[7];
    const float* W3 = (const float*)d_in[8];
    const float* b3 = (const float*)d_in[9];
    const float* W4 = (const float*)d_in[10];
    const float* b4 = (const float*)d_in[11];
    const float* W5 = (const float*)d_in[12];
    const float* b5 = (const float*)d_in[13];
    const float* W6 = (const float*)d_in[14];
    const float* b6 = (const float*)d_in[15];
    float* out = (float*)d_out;

    const int n = in_sizes[0];
    const int e = in_sizes[2];

    const int nb  = (n + 255) / 256;
    const int ebk = (e + 255) / 256;
    const int nchunks = (n + 1023) / 1024;

    k_init_detect<<<nb, 256>>>((const int*)ei, n);
    k_edges_pre<<<ebk, 256>>>(ei, ew, e);
    k_scan1<<<nchunks, 1024>>>(n);
    k_scan2<<<1, 1024>>>(nchunks);
    k_scan3_dis<<<nb, 256>>>(x, n);
    k_norm_fill<<<ebk, 256>>>(ew, x, e);

    const int gx = (n + 63) / 64;

    __half* A; __half* B; __half* C;
    cudaGetSymbolAddress((void**)&A, g_A);
    cudaGetSymbolAddress((void**)&B, g_B);
    cudaGetSymbolAddress((void**)&C, g_C);

    // layer 2 (fused layer-1 expand): t2->B, gather -> C
    k_gemm2_mma<<<gx, 128>>>(W1, b1, W2, B, n);
    k_gather<96><<<(n * 24 + 255) / 256, 256>>>(B, C, n);

    // layer 3: in C (+b2,relu) -> t3->A, gather -> B
    k_gemm_mma<96, 64><<<gx, 128>>>(C, b2, W3, A, n);
    k_gather<64><<<(n * 16 + 255) / 256, 256>>>(A, B, n);

    // layer 4: in B (+b3,relu) -> t4->C, gather fused with pool -> g_pool
    k_gemm_mma<64, 32><<<gx, 128>>>(B, b3, W4, C, n);
    k_gather_pool<<<(n * 8 + 255) / 256, 256>>>(C, b4, bt, n);

    // MLP
    k_mlp<<<1, 64>>>(W5, b5, W6, b6, out);
}